// round 1
// baseline (speedup 1.0000x reference)
#include <cuda_runtime.h>
#include <math.h>

// Problem constants
#define BB 2
#define TT 2048
#define DD 2048
#define NH 32
#define NKV 8
#define DH 64
#define GG 4   // NH / NKV

// Scratch (device globals: no allocation allowed)
__device__ float g_q[BB * TT * DD];            // [B*T, H*DH]
__device__ float g_k[BB * TT * NKV * DH];      // [B*T, HKV*DH]
__device__ float g_v[BB * TT * NKV * DH];
__device__ float g_ctx[BB * TT * DD];          // [B*T, H*DH]

// ---------------------------------------------------------------------------
// SGEMM: C[M,N] = A[M,K] @ B[K,N], all row-major fp32.
// 128x128 block tile, BK=8, 8x8 per thread, 256 threads.
// All dims are multiples of the tile sizes for this problem.
// ---------------------------------------------------------------------------
__global__ __launch_bounds__(256) void sgemm128(
    int M, int N, int K,
    const float* __restrict__ A, const float* __restrict__ B,
    float* __restrict__ C)
{
    const int BM = 128, BN = 128, BK = 8;
    __shared__ float As[BK][BM];
    __shared__ float Bs[BK][BN];

    int tid = threadIdx.x;
    int tx = tid & 15;      // 0..15 (col group)
    int ty = tid >> 4;      // 0..15 (row group)
    int rowBase = blockIdx.y * BM;
    int colBase = blockIdx.x * BN;

    // A load: 128x8 tile, each thread one float4 (transposed store)
    int aRow = tid >> 1;           // 0..127
    int aCol = (tid & 1) * 4;      // 0 or 4
    // B load: 8x128 tile, each thread one float4
    int bRow = tid >> 5;           // 0..7
    int bCol = (tid & 31) * 4;     // 0..124

    const float* Aptr = A + (size_t)(rowBase + aRow) * K + aCol;
    const float* Bptr = B + (size_t)bRow * N + colBase + bCol;

    float acc[8][8];
#pragma unroll
    for (int i = 0; i < 8; i++)
#pragma unroll
        for (int j = 0; j < 8; j++) acc[i][j] = 0.f;

    for (int k0 = 0; k0 < K; k0 += BK) {
        float4 a4 = *(const float4*)(Aptr + k0);
        As[aCol + 0][aRow] = a4.x;
        As[aCol + 1][aRow] = a4.y;
        As[aCol + 2][aRow] = a4.z;
        As[aCol + 3][aRow] = a4.w;
        *(float4*)&Bs[bRow][bCol] = *(const float4*)(Bptr + (size_t)k0 * N);
        __syncthreads();

#pragma unroll
        for (int kk = 0; kk < BK; kk++) {
            float ra[8], rb[8];
            float4 t0 = *(const float4*)&As[kk][ty * 8];
            float4 t1 = *(const float4*)&As[kk][ty * 8 + 4];
            ra[0] = t0.x; ra[1] = t0.y; ra[2] = t0.z; ra[3] = t0.w;
            ra[4] = t1.x; ra[5] = t1.y; ra[6] = t1.z; ra[7] = t1.w;
            float4 u0 = *(const float4*)&Bs[kk][tx * 8];
            float4 u1 = *(const float4*)&Bs[kk][tx * 8 + 4];
            rb[0] = u0.x; rb[1] = u0.y; rb[2] = u0.z; rb[3] = u0.w;
            rb[4] = u1.x; rb[5] = u1.y; rb[6] = u1.z; rb[7] = u1.w;
#pragma unroll
            for (int i = 0; i < 8; i++)
#pragma unroll
                for (int j = 0; j < 8; j++)
                    acc[i][j] += ra[i] * rb[j];
        }
        __syncthreads();
    }

#pragma unroll
    for (int i = 0; i < 8; i++) {
        float* crow = C + (size_t)(rowBase + ty * 8 + i) * N + colBase + tx * 8;
        float4 o0 = make_float4(acc[i][0], acc[i][1], acc[i][2], acc[i][3]);
        float4 o1 = make_float4(acc[i][4], acc[i][5], acc[i][6], acc[i][7]);
        *(float4*)(crow) = o0;
        *(float4*)(crow + 4) = o1;
    }
}

// ---------------------------------------------------------------------------
// RoPE in-place on X: [B*T, nheads*64].
// One thread per (n, h, i) pair, i in 0..31.
// out[i]    = x[i]*cos - x[i+32]*sin
// out[i+32] = x[i+32]*cos + x[i]*sin
// angle = t * 10000^(-i/32)
// ---------------------------------------------------------------------------
__global__ void rope_kernel(float* __restrict__ X, int nheads, int total)
{
    int idx = blockIdx.x * blockDim.x + threadIdx.x;
    if (idx >= total) return;
    int i = idx & 31;
    int rest = idx >> 5;
    int h = rest % nheads;
    int n = rest / nheads;           // b*T + t
    int t = n & (TT - 1);

    // inv_freq in double for accuracy, then fp32 angle like the reference
    double inv = exp(-(double)i * (9.210340371976184 / 32.0)); // ln(10000)=9.2103...
    float ang = (float)t * (float)inv;
    float c, s;
    sincosf(ang, &s, &c);

    float* p = X + (size_t)n * nheads * 64 + h * 64;
    float x1 = p[i];
    float x2 = p[i + 32];
    p[i]      = x1 * c - x2 * s;
    p[i + 32] = x2 * c + x1 * s;
}

// ---------------------------------------------------------------------------
// Flash attention (causal, GQA): one block per (q-tile of 128 rows, head, batch).
// 128 threads; each thread owns one q row: q[64] and o[64] in registers.
// K/V tiles (32 x 64) staged in SMEM; all reads are warp-broadcast.
// ---------------------------------------------------------------------------
#define ATT_BM 128
#define ATT_BN 32

__global__ __launch_bounds__(128) void flash_attn(
    const float* __restrict__ Q, const float* __restrict__ K,
    const float* __restrict__ V, float* __restrict__ O)
{
    __shared__ float Ks[ATT_BN][64];
    __shared__ float Vs[ATT_BN][64];

    int tid = threadIdx.x;           // 0..127
    int qt = blockIdx.x;             // q tile
    int h  = blockIdx.y;             // query head
    int b  = blockIdx.z;
    int t  = qt * ATT_BM + tid;      // this thread's query position
    int kh = h / GG;

    const float scale = 0.125f;      // 1/sqrt(64)

    float q[64];
    const float* qp = Q + ((size_t)(b * TT + t) * NH + h) * DH;
#pragma unroll
    for (int d = 0; d < 64; d += 4) {
        float4 v4 = *(const float4*)(qp + d);
        q[d]     = v4.x * scale;
        q[d + 1] = v4.y * scale;
        q[d + 2] = v4.z * scale;
        q[d + 3] = v4.w * scale;
    }

    float o[64];
#pragma unroll
    for (int d = 0; d < 64; d++) o[d] = 0.f;
    float m = -1e30f, l = 0.f;

    // smem load indices
    int lr = tid >> 2;               // 0..31 (row)
    int lc = (tid & 3) * 16;         // 0,16,32,48

    int kend = (qt + 1) * ATT_BM;    // exclusive causal bound for this tile

    for (int s0 = 0; s0 < kend; s0 += ATT_BN) {
        const float* kp = K + ((size_t)(b * TT + s0 + lr) * NKV + kh) * DH + lc;
        const float* vp = V + ((size_t)(b * TT + s0 + lr) * NKV + kh) * DH + lc;
#pragma unroll
        for (int u = 0; u < 16; u += 4) {
            *(float4*)&Ks[lr][lc + u] = *(const float4*)(kp + u);
            *(float4*)&Vs[lr][lc + u] = *(const float4*)(vp + u);
        }
        __syncthreads();

        float sc[ATT_BN];
#pragma unroll
        for (int j = 0; j < ATT_BN; j++) {
            float acc = 0.f;
#pragma unroll
            for (int d = 0; d < 64; d += 4) {
                float4 kv = *(const float4*)&Ks[j][d];
                acc += q[d] * kv.x + q[d + 1] * kv.y
                     + q[d + 2] * kv.z + q[d + 3] * kv.w;
            }
            sc[j] = (s0 + j <= t) ? acc : -1e30f;
        }

        float mt = m;
#pragma unroll
        for (int j = 0; j < ATT_BN; j++) mt = fmaxf(mt, sc[j]);

        float corr = __expf(m - mt);
        l *= corr;
#pragma unroll
        for (int d = 0; d < 64; d++) o[d] *= corr;

#pragma unroll
        for (int j = 0; j < ATT_BN; j++) {
            float p = __expf(sc[j] - mt);
            l += p;
#pragma unroll
            for (int d = 0; d < 64; d += 4) {
                float4 vv = *(const float4*)&Vs[j][d];
                o[d]     += p * vv.x;
                o[d + 1] += p * vv.y;
                o[d + 2] += p * vv.z;
                o[d + 3] += p * vv.w;
            }
        }
        m = mt;
        __syncthreads();
    }

    float inv_l = 1.f / l;
    float* op = O + ((size_t)(b * TT + t) * NH + h) * DH;
#pragma unroll
    for (int d = 0; d < 64; d += 4) {
        float4 o4 = make_float4(o[d] * inv_l, o[d + 1] * inv_l,
                                o[d + 2] * inv_l, o[d + 3] * inv_l);
        *(float4*)(op + d) = o4;
    }
}

// ---------------------------------------------------------------------------
// Launch
// ---------------------------------------------------------------------------
extern "C" void kernel_launch(void* const* d_in, const int* in_sizes, int n_in,
                              void* d_out, int out_size)
{
    const float* x  = (const float*)d_in[0];
    const float* Wq = (const float*)d_in[1];
    const float* Wk = (const float*)d_in[2];
    const float* Wv = (const float*)d_in[3];
    const float* Wo = (const float*)d_in[4];
    float* out = (float*)d_out;

    float *q, *k, *v, *ctx;
    cudaGetSymbolAddress((void**)&q,   g_q);
    cudaGetSymbolAddress((void**)&k,   g_k);
    cudaGetSymbolAddress((void**)&v,   g_v);
    cudaGetSymbolAddress((void**)&ctx, g_ctx);

    const int M = BB * TT;   // 4096

    // Projections
    sgemm128<<<dim3(DD / 128, M / 128), 256>>>(M, DD, DD, x, Wq, q);
    sgemm128<<<dim3((NKV * DH) / 128, M / 128), 256>>>(M, NKV * DH, DD, x, Wk, k);
    sgemm128<<<dim3((NKV * DH) / 128, M / 128), 256>>>(M, NKV * DH, DD, x, Wv, v);

    // RoPE (in place)
    {
        int totq = M * NH * 32;
        rope_kernel<<<(totq + 255) / 256, 256>>>(q, NH, totq);
        int totk = M * NKV * 32;
        rope_kernel<<<(totk + 255) / 256, 256>>>(k, NKV, totk);
    }

    // Attention
    flash_attn<<<dim3(TT / ATT_BM, NH, BB), 128>>>(q, k, v, ctx);

    // Output projection
    sgemm128<<<dim3(DD / 128, M / 128), 256>>>(M, DD, DD, ctx, Wo, out);
}

// round 2
// speedup vs baseline: 1.4968x; 1.4968x over previous
#include <cuda_runtime.h>
#include <math.h>
#include <stdint.h>

// Problem constants
#define BB 2
#define TT 2048
#define DD 2048
#define NH 32
#define NKV 8
#define DH 64
#define GG 4   // NH / NKV

// Scratch (device globals: no allocation allowed)
__device__ float g_q[BB * TT * DD];            // [B*T, H*DH]
__device__ float g_k[BB * TT * NKV * DH];      // [B*T, HKV*DH]
__device__ float g_v[BB * TT * NKV * DH];
__device__ float g_ctx[BB * TT * DD];          // [B*T, H*DH]

// ---------------------------------------------------------------------------
// TF32 tensor-core GEMM: C[M,N] = A[M,K] @ B[K,N], row-major fp32 in/out.
// 128x128 block tile, BK=16, 256 threads = 8 warps, warp tile 64x32,
// mma.sync.m16n8k8.tf32 with cvt.rna on SMEM store.
// All dims multiples of tile sizes for this problem.
// ---------------------------------------------------------------------------
#define GBM 128
#define GBN 128
#define GBK 16
#define GSTRIDE 136   // +8 pad: bank = 8*t + g -> conflict-free frag loads

__device__ __forceinline__ uint32_t f2tf32(float f) {
    uint32_t u;
    asm("cvt.rna.tf32.f32 %0, %1;" : "=r"(u) : "f"(f));
    return u;
}

__global__ __launch_bounds__(256) void gemm_tf32(
    int M, int N, int K,
    const float* __restrict__ A, const float* __restrict__ B,
    float* __restrict__ C)
{
    __shared__ uint32_t As[GBK][GSTRIDE];
    __shared__ uint32_t Bs[GBK][GSTRIDE];

    const int tid = threadIdx.x;
    const int lane = tid & 31;
    const int warp = tid >> 5;
    const int g = lane >> 2;     // groupID 0..7
    const int t = lane & 3;      // thread-in-group 0..3
    const int warpRow = warp & 1;    // 2 warp rows of 64
    const int warpCol = warp >> 1;   // 4 warp cols of 32

    const int rowBase = blockIdx.y * GBM;
    const int colBase = blockIdx.x * GBN;

    float acc[4][4][4];
#pragma unroll
    for (int mi = 0; mi < 4; mi++)
#pragma unroll
        for (int ni = 0; ni < 4; ni++)
#pragma unroll
            for (int r = 0; r < 4; r++) acc[mi][ni][r] = 0.f;

    for (int k0 = 0; k0 < K; k0 += GBK) {
        // Load A tile: 128 rows x 16 cols -> As[col][row] (transposed)
#pragma unroll
        for (int i = 0; i < 2; i++) {
            int idx = tid + i * 256;            // 0..511
            int row = idx >> 2;                 // 0..127
            int c4 = (idx & 3) * 4;             // 0,4,8,12
            float4 a4 = *(const float4*)(A + (size_t)(rowBase + row) * K + k0 + c4);
            As[c4 + 0][row] = f2tf32(a4.x);
            As[c4 + 1][row] = f2tf32(a4.y);
            As[c4 + 2][row] = f2tf32(a4.z);
            As[c4 + 3][row] = f2tf32(a4.w);
        }
        // Load B tile: 16 rows x 128 cols -> Bs[row][col]
#pragma unroll
        for (int i = 0; i < 2; i++) {
            int idx = tid + i * 256;
            int row = idx >> 5;                 // 0..15
            int c4 = (idx & 31) * 4;            // 0..124
            float4 b4 = *(const float4*)(B + (size_t)(k0 + row) * N + colBase + c4);
            uint4 u;
            u.x = f2tf32(b4.x); u.y = f2tf32(b4.y);
            u.z = f2tf32(b4.z); u.w = f2tf32(b4.w);
            *(uint4*)&Bs[row][c4] = u;
        }
        __syncthreads();

#pragma unroll
        for (int ks = 0; ks < GBK; ks += 8) {
            uint32_t af[4][4];
            uint32_t bf[4][2];
#pragma unroll
            for (int mi = 0; mi < 4; mi++) {
                int rb = warpRow * 64 + mi * 16;
                af[mi][0] = As[ks + t][rb + g];
                af[mi][1] = As[ks + t][rb + g + 8];
                af[mi][2] = As[ks + t + 4][rb + g];
                af[mi][3] = As[ks + t + 4][rb + g + 8];
            }
#pragma unroll
            for (int ni = 0; ni < 4; ni++) {
                int cb = warpCol * 32 + ni * 8 + g;
                bf[ni][0] = Bs[ks + t][cb];
                bf[ni][1] = Bs[ks + t + 4][cb];
            }
#pragma unroll
            for (int mi = 0; mi < 4; mi++)
#pragma unroll
                for (int ni = 0; ni < 4; ni++) {
                    asm volatile(
                        "mma.sync.aligned.m16n8k8.row.col.f32.tf32.tf32.f32 "
                        "{%0,%1,%2,%3}, {%4,%5,%6,%7}, {%8,%9}, {%0,%1,%2,%3};"
                        : "+f"(acc[mi][ni][0]), "+f"(acc[mi][ni][1]),
                          "+f"(acc[mi][ni][2]), "+f"(acc[mi][ni][3])
                        : "r"(af[mi][0]), "r"(af[mi][1]),
                          "r"(af[mi][2]), "r"(af[mi][3]),
                          "r"(bf[ni][0]), "r"(bf[ni][1]));
                }
        }
        __syncthreads();
    }

    // Epilogue: c0:(g,2t) c1:(g,2t+1) c2:(g+8,2t) c3:(g+8,2t+1)
#pragma unroll
    for (int mi = 0; mi < 4; mi++) {
#pragma unroll
        for (int ni = 0; ni < 4; ni++) {
            int r0 = rowBase + warpRow * 64 + mi * 16 + g;
            int col = colBase + warpCol * 32 + ni * 8 + 2 * t;
            float2 lo = make_float2(acc[mi][ni][0], acc[mi][ni][1]);
            float2 hi = make_float2(acc[mi][ni][2], acc[mi][ni][3]);
            *(float2*)(C + (size_t)r0 * N + col) = lo;
            *(float2*)(C + (size_t)(r0 + 8) * N + col) = hi;
        }
    }
}

// ---------------------------------------------------------------------------
// RoPE in-place on X: [B*T, nheads*64].
// ---------------------------------------------------------------------------
__global__ void rope_kernel(float* __restrict__ X, int nheads, int total)
{
    int idx = blockIdx.x * blockDim.x + threadIdx.x;
    if (idx >= total) return;
    int i = idx & 31;
    int rest = idx >> 5;
    int h = rest % nheads;
    int n = rest / nheads;           // b*T + t
    int t = n & (TT - 1);

    double inv = exp(-(double)i * (9.210340371976184 / 32.0)); // ln(10000)
    float ang = (float)t * (float)inv;
    float c, s;
    sincosf(ang, &s, &c);

    float* p = X + (size_t)n * nheads * 64 + h * 64;
    float x1 = p[i];
    float x2 = p[i + 32];
    p[i]      = x1 * c - x2 * s;
    p[i + 32] = x2 * c + x1 * s;
}

// ---------------------------------------------------------------------------
// Flash attention (causal, GQA): one block per (q-tile of 128 rows, head, batch).
// ---------------------------------------------------------------------------
#define ATT_BM 128
#define ATT_BN 32

__global__ __launch_bounds__(128) void flash_attn(
    const float* __restrict__ Q, const float* __restrict__ K,
    const float* __restrict__ V, float* __restrict__ O)
{
    __shared__ float Ks[ATT_BN][64];
    __shared__ float Vs[ATT_BN][64];

    int tid = threadIdx.x;           // 0..127
    int qt = blockIdx.x;             // q tile
    int h  = blockIdx.y;             // query head
    int b  = blockIdx.z;
    int t  = qt * ATT_BM + tid;      // this thread's query position
    int kh = h / GG;

    const float scale = 0.125f;      // 1/sqrt(64)

    float q[64];
    const float* qp = Q + ((size_t)(b * TT + t) * NH + h) * DH;
#pragma unroll
    for (int d = 0; d < 64; d += 4) {
        float4 v4 = *(const float4*)(qp + d);
        q[d]     = v4.x * scale;
        q[d + 1] = v4.y * scale;
        q[d + 2] = v4.z * scale;
        q[d + 3] = v4.w * scale;
    }

    float o[64];
#pragma unroll
    for (int d = 0; d < 64; d++) o[d] = 0.f;
    float m = -1e30f, l = 0.f;

    int lr = tid >> 2;               // 0..31 (row)
    int lc = (tid & 3) * 16;         // 0,16,32,48

    int kend = (qt + 1) * ATT_BM;    // exclusive causal bound for this tile

    for (int s0 = 0; s0 < kend; s0 += ATT_BN) {
        const float* kp = K + ((size_t)(b * TT + s0 + lr) * NKV + kh) * DH + lc;
        const float* vp = V + ((size_t)(b * TT + s0 + lr) * NKV + kh) * DH + lc;
#pragma unroll
        for (int u = 0; u < 16; u += 4) {
            *(float4*)&Ks[lr][lc + u] = *(const float4*)(kp + u);
            *(float4*)&Vs[lr][lc + u] = *(const float4*)(vp + u);
        }
        __syncthreads();

        float sc[ATT_BN];
#pragma unroll
        for (int j = 0; j < ATT_BN; j++) {
            float acc = 0.f;
#pragma unroll
            for (int d = 0; d < 64; d += 4) {
                float4 kv = *(const float4*)&Ks[j][d];
                acc += q[d] * kv.x + q[d + 1] * kv.y
                     + q[d + 2] * kv.z + q[d + 3] * kv.w;
            }
            sc[j] = (s0 + j <= t) ? acc : -1e30f;
        }

        float mt = m;
#pragma unroll
        for (int j = 0; j < ATT_BN; j++) mt = fmaxf(mt, sc[j]);

        float corr = __expf(m - mt);
        l *= corr;
#pragma unroll
        for (int d = 0; d < 64; d++) o[d] *= corr;

#pragma unroll
        for (int j = 0; j < ATT_BN; j++) {
            float p = __expf(sc[j] - mt);
            l += p;
#pragma unroll
            for (int d = 0; d < 64; d += 4) {
                float4 vv = *(const float4*)&Vs[j][d];
                o[d]     += p * vv.x;
                o[d + 1] += p * vv.y;
                o[d + 2] += p * vv.z;
                o[d + 3] += p * vv.w;
            }
        }
        m = mt;
        __syncthreads();
    }

    float inv_l = 1.f / l;
    float* op = O + ((size_t)(b * TT + t) * NH + h) * DH;
#pragma unroll
    for (int d = 0; d < 64; d += 4) {
        float4 o4 = make_float4(o[d] * inv_l, o[d + 1] * inv_l,
                                o[d + 2] * inv_l, o[d + 3] * inv_l);
        *(float4*)(op + d) = o4;
    }
}

// ---------------------------------------------------------------------------
// Launch
// ---------------------------------------------------------------------------
extern "C" void kernel_launch(void* const* d_in, const int* in_sizes, int n_in,
                              void* d_out, int out_size)
{
    const float* x  = (const float*)d_in[0];
    const float* Wq = (const float*)d_in[1];
    const float* Wk = (const float*)d_in[2];
    const float* Wv = (const float*)d_in[3];
    const float* Wo = (const float*)d_in[4];
    float* out = (float*)d_out;

    float *q, *k, *v, *ctx;
    cudaGetSymbolAddress((void**)&q,   g_q);
    cudaGetSymbolAddress((void**)&k,   g_k);
    cudaGetSymbolAddress((void**)&v,   g_v);
    cudaGetSymbolAddress((void**)&ctx, g_ctx);

    const int M = BB * TT;   // 4096

    // Projections (tf32 tensor cores)
    gemm_tf32<<<dim3(DD / GBN, M / GBM), 256>>>(M, DD, DD, x, Wq, q);
    gemm_tf32<<<dim3((NKV * DH) / GBN, M / GBM), 256>>>(M, NKV * DH, DD, x, Wk, k);
    gemm_tf32<<<dim3((NKV * DH) / GBN, M / GBM), 256>>>(M, NKV * DH, DD, x, Wv, v);

    // RoPE (in place)
    {
        int totq = M * NH * 32;
        rope_kernel<<<(totq + 255) / 256, 256>>>(q, NH, totq);
        int totk = M * NKV * 32;
        rope_kernel<<<(totk + 255) / 256, 256>>>(k, NKV, totk);
    }

    // Attention
    flash_attn<<<dim3(TT / ATT_BM, NH, BB), 128>>>(q, k, v, ctx);

    // Output projection
    gemm_tf32<<<dim3(DD / GBN, M / GBM), 256>>>(M, DD, DD, ctx, Wo, out);
}

// round 3
// speedup vs baseline: 3.3261x; 2.2222x over previous
#include <cuda_runtime.h>
#include <math.h>
#include <stdint.h>

// Problem constants
#define BB 2
#define TT 2048
#define DD 2048
#define NH 32
#define NKV 8
#define DH 64
#define GG 4   // NH / NKV

// Scratch (device globals: no allocation allowed)
__device__ float g_q[BB * TT * DD];            // [B*T, H*DH]
__device__ float g_k[BB * TT * NKV * DH];      // [B*T, HKV*DH]
__device__ float g_v[BB * TT * NKV * DH];
__device__ float g_ctx[BB * TT * DD];          // [B*T, H*DH]

__device__ __forceinline__ uint32_t f2tf32(float f) {
    uint32_t u;
    asm("cvt.rna.tf32.f32 %0, %1;" : "=r"(u) : "f"(f));
    return u;
}

__device__ __forceinline__ void mma_tf32(
    float& d0, float& d1, float& d2, float& d3,
    uint32_t a0, uint32_t a1, uint32_t a2, uint32_t a3,
    uint32_t b0, uint32_t b1)
{
    asm volatile(
        "mma.sync.aligned.m16n8k8.row.col.f32.tf32.tf32.f32 "
        "{%0,%1,%2,%3}, {%4,%5,%6,%7}, {%8,%9}, {%0,%1,%2,%3};"
        : "+f"(d0), "+f"(d1), "+f"(d2), "+f"(d3)
        : "r"(a0), "r"(a1), "r"(a2), "r"(a3), "r"(b0), "r"(b1));
}

// ---------------------------------------------------------------------------
// TF32 tensor-core GEMM: C[M,N] = A[M,K] @ B[K,N], row-major fp32 in/out.
// 128x128 block tile, BK=16, 256 threads = 8 warps, warp tile 64x32.
// ---------------------------------------------------------------------------
#define GBM 128
#define GBN 128
#define GBK 16
#define GSTRIDE 136

__global__ __launch_bounds__(256) void gemm_tf32(
    int M, int N, int K,
    const float* __restrict__ A, const float* __restrict__ B,
    float* __restrict__ C)
{
    __shared__ uint32_t As[GBK][GSTRIDE];
    __shared__ uint32_t Bs[GBK][GSTRIDE];

    const int tid = threadIdx.x;
    const int lane = tid & 31;
    const int warp = tid >> 5;
    const int g = lane >> 2;
    const int t = lane & 3;
    const int warpRow = warp & 1;
    const int warpCol = warp >> 1;

    const int rowBase = blockIdx.y * GBM;
    const int colBase = blockIdx.x * GBN;

    float acc[4][4][4];
#pragma unroll
    for (int mi = 0; mi < 4; mi++)
#pragma unroll
        for (int ni = 0; ni < 4; ni++)
#pragma unroll
            for (int r = 0; r < 4; r++) acc[mi][ni][r] = 0.f;

    for (int k0 = 0; k0 < K; k0 += GBK) {
#pragma unroll
        for (int i = 0; i < 2; i++) {
            int idx = tid + i * 256;
            int row = idx >> 2;
            int c4 = (idx & 3) * 4;
            float4 a4 = *(const float4*)(A + (size_t)(rowBase + row) * K + k0 + c4);
            As[c4 + 0][row] = f2tf32(a4.x);
            As[c4 + 1][row] = f2tf32(a4.y);
            As[c4 + 2][row] = f2tf32(a4.z);
            As[c4 + 3][row] = f2tf32(a4.w);
        }
#pragma unroll
        for (int i = 0; i < 2; i++) {
            int idx = tid + i * 256;
            int row = idx >> 5;
            int c4 = (idx & 31) * 4;
            float4 b4 = *(const float4*)(B + (size_t)(k0 + row) * N + colBase + c4);
            uint4 u;
            u.x = f2tf32(b4.x); u.y = f2tf32(b4.y);
            u.z = f2tf32(b4.z); u.w = f2tf32(b4.w);
            *(uint4*)&Bs[row][c4] = u;
        }
        __syncthreads();

#pragma unroll
        for (int ks = 0; ks < GBK; ks += 8) {
            uint32_t af[4][4];
            uint32_t bf[4][2];
#pragma unroll
            for (int mi = 0; mi < 4; mi++) {
                int rb = warpRow * 64 + mi * 16;
                af[mi][0] = As[ks + t][rb + g];
                af[mi][1] = As[ks + t][rb + g + 8];
                af[mi][2] = As[ks + t + 4][rb + g];
                af[mi][3] = As[ks + t + 4][rb + g + 8];
            }
#pragma unroll
            for (int ni = 0; ni < 4; ni++) {
                int cb = warpCol * 32 + ni * 8 + g;
                bf[ni][0] = Bs[ks + t][cb];
                bf[ni][1] = Bs[ks + t + 4][cb];
            }
#pragma unroll
            for (int mi = 0; mi < 4; mi++)
#pragma unroll
                for (int ni = 0; ni < 4; ni++)
                    mma_tf32(acc[mi][ni][0], acc[mi][ni][1],
                             acc[mi][ni][2], acc[mi][ni][3],
                             af[mi][0], af[mi][1], af[mi][2], af[mi][3],
                             bf[ni][0], bf[ni][1]);
        }
        __syncthreads();
    }

#pragma unroll
    for (int mi = 0; mi < 4; mi++) {
#pragma unroll
        for (int ni = 0; ni < 4; ni++) {
            int r0 = rowBase + warpRow * 64 + mi * 16 + g;
            int col = colBase + warpCol * 32 + ni * 8 + 2 * t;
            *(float2*)(C + (size_t)r0 * N + col) =
                make_float2(acc[mi][ni][0], acc[mi][ni][1]);
            *(float2*)(C + (size_t)(r0 + 8) * N + col) =
                make_float2(acc[mi][ni][2], acc[mi][ni][3]);
        }
    }
}

// ---------------------------------------------------------------------------
// RoPE in-place on X: [B*T, nheads*64].
// ---------------------------------------------------------------------------
__global__ void rope_kernel(float* __restrict__ X, int nheads, int total)
{
    int idx = blockIdx.x * blockDim.x + threadIdx.x;
    if (idx >= total) return;
    int i = idx & 31;
    int rest = idx >> 5;
    int h = rest % nheads;
    int n = rest / nheads;           // b*T + t
    int t = n & (TT - 1);

    double inv = exp(-(double)i * (9.210340371976184 / 32.0)); // ln(10000)
    float ang = (float)t * (float)inv;
    float c, s;
    sincosf(ang, &s, &c);

    float* p = X + (size_t)n * nheads * 64 + h * 64;
    float x1 = p[i];
    float x2 = p[i + 32];
    p[i]      = x1 * c - x2 * s;
    p[i + 32] = x2 * c + x1 * s;
}

// ---------------------------------------------------------------------------
// Tensor-core flash attention (causal, GQA).
// Block: 128 q rows x (head, batch). 256 threads = 8 warps; warp owns 16 rows.
// Per iter: 64 kv positions. S = Q@K^T (tf32 mma), online softmax in C-frag
// layout, P relayout to A-frag via shuffles, O += P@V (tf32 mma).
// Ks stride 68 (bank 4g+t conflict-free), Vs stride 72 (bank 8t+g).
// ---------------------------------------------------------------------------
__global__ __launch_bounds__(256) void flash_attn_tc(
    const float* __restrict__ Q, const float* __restrict__ K,
    const float* __restrict__ V, float* __restrict__ O)
{
    __shared__ float Ks[64][68];
    __shared__ float Vs[64][72];

    const int tid = threadIdx.x;
    const int lane = tid & 31;
    const int warp = tid >> 5;
    const int g = lane >> 2;
    const int t = lane & 3;
    const int qt = blockIdx.x;
    const int h  = blockIdx.y;
    const int b  = blockIdx.z;
    const int kh = h / GG;
    const int rowBase = qt * 128 + warp * 16;   // warp's first q row

    // ---- stage Q (two 64-row halves through Vs), extract A fragments ----
    uint32_t qa[8][4];
#pragma unroll
    for (int half = 0; half < 2; half++) {
#pragma unroll
        for (int i = 0; i < 4; i++) {
            int lin = tid + i * 256;
            int r = lin >> 4;
            int c4 = (lin & 15) * 4;
            const float* src = Q + (size_t)(b * TT + qt * 128 + half * 64 + r) * DD
                                 + h * DH + c4;
            *(float4*)&Vs[r][c4] = *(const float4*)src;
        }
        __syncthreads();
        if ((warp >> 2) == half) {
            int lr = (warp & 3) * 16 + g;
#pragma unroll
            for (int kc = 0; kc < 8; kc++) {
                qa[kc][0] = f2tf32(Vs[lr][kc * 8 + t] * 0.125f);
                qa[kc][1] = f2tf32(Vs[lr + 8][kc * 8 + t] * 0.125f);
                qa[kc][2] = f2tf32(Vs[lr][kc * 8 + t + 4] * 0.125f);
                qa[kc][3] = f2tf32(Vs[lr + 8][kc * 8 + t + 4] * 0.125f);
            }
        }
        __syncthreads();
    }

    float oacc[8][4];
#pragma unroll
    for (int ni = 0; ni < 8; ni++)
#pragma unroll
        for (int r = 0; r < 4; r++) oacc[ni][r] = 0.f;
    float m0 = -1e30f, m1 = -1e30f, l0 = 0.f, l1 = 0.f;

    const int kend = (qt + 1) * 128;
    const int srcA = (lane & 28) | (t >> 1);   // 4g + t/2
    const bool odd = (t & 1);

    for (int s0 = 0; s0 < kend; s0 += 64) {
        // load K, V tiles (64 x 64 each)
#pragma unroll
        for (int i = 0; i < 4; i++) {
            int lin = tid + i * 256;
            int r = lin >> 4;
            int c4 = (lin & 15) * 4;
            size_t base = (size_t)(b * TT + s0 + r) * (NKV * DH) + kh * DH + c4;
            float4 kk = *(const float4*)(K + base);
            float4 vv = *(const float4*)(V + base);
            Ks[r][c4 + 0] = __uint_as_float(f2tf32(kk.x));
            Ks[r][c4 + 1] = __uint_as_float(f2tf32(kk.y));
            Ks[r][c4 + 2] = __uint_as_float(f2tf32(kk.z));
            Ks[r][c4 + 3] = __uint_as_float(f2tf32(kk.w));
            Vs[r][c4 + 0] = __uint_as_float(f2tf32(vv.x));
            Vs[r][c4 + 1] = __uint_as_float(f2tf32(vv.y));
            Vs[r][c4 + 2] = __uint_as_float(f2tf32(vv.z));
            Vs[r][c4 + 3] = __uint_as_float(f2tf32(vv.w));
        }
        __syncthreads();

        if (s0 <= rowBase + 15) {   // warp has at least one unmasked element
            // ---- S = Q @ K^T ----
            float sacc[8][4];
#pragma unroll
            for (int ni = 0; ni < 8; ni++) {
                sacc[ni][0] = 0.f; sacc[ni][1] = 0.f;
                sacc[ni][2] = 0.f; sacc[ni][3] = 0.f;
#pragma unroll
                for (int kc = 0; kc < 8; kc++) {
                    uint32_t b0 = __float_as_uint(Ks[ni * 8 + g][kc * 8 + t]);
                    uint32_t b1 = __float_as_uint(Ks[ni * 8 + g][kc * 8 + t + 4]);
                    mma_tf32(sacc[ni][0], sacc[ni][1], sacc[ni][2], sacc[ni][3],
                             qa[kc][0], qa[kc][1], qa[kc][2], qa[kc][3], b0, b1);
                }
            }

            // ---- causal mask (only near diagonal) ----
            if (s0 + 63 > rowBase) {
                int r0 = rowBase + g;
                int r1 = r0 + 8;
#pragma unroll
                for (int ni = 0; ni < 8; ni++) {
                    int c = s0 + ni * 8 + 2 * t;
                    if (c > r0)     sacc[ni][0] = -1e30f;
                    if (c + 1 > r0) sacc[ni][1] = -1e30f;
                    if (c > r1)     sacc[ni][2] = -1e30f;
                    if (c + 1 > r1) sacc[ni][3] = -1e30f;
                }
            }

            // ---- online softmax ----
            float mx0 = -1e30f, mx1 = -1e30f;
#pragma unroll
            for (int ni = 0; ni < 8; ni++) {
                mx0 = fmaxf(mx0, fmaxf(sacc[ni][0], sacc[ni][1]));
                mx1 = fmaxf(mx1, fmaxf(sacc[ni][2], sacc[ni][3]));
            }
            mx0 = fmaxf(mx0, __shfl_xor_sync(0xffffffffu, mx0, 1));
            mx0 = fmaxf(mx0, __shfl_xor_sync(0xffffffffu, mx0, 2));
            mx1 = fmaxf(mx1, __shfl_xor_sync(0xffffffffu, mx1, 1));
            mx1 = fmaxf(mx1, __shfl_xor_sync(0xffffffffu, mx1, 2));

            float mn0 = fmaxf(m0, mx0), mn1 = fmaxf(m1, mx1);
            float cr0 = __expf(m0 - mn0), cr1 = __expf(m1 - mn1);
            m0 = mn0; m1 = mn1;
            l0 *= cr0; l1 *= cr1;
#pragma unroll
            for (int ni = 0; ni < 8; ni++) {
                oacc[ni][0] *= cr0; oacc[ni][1] *= cr0;
                oacc[ni][2] *= cr1; oacc[ni][3] *= cr1;
            }
#pragma unroll
            for (int ni = 0; ni < 8; ni++) {
                sacc[ni][0] = __expf(sacc[ni][0] - m0);
                sacc[ni][1] = __expf(sacc[ni][1] - m0);
                sacc[ni][2] = __expf(sacc[ni][2] - m1);
                sacc[ni][3] = __expf(sacc[ni][3] - m1);
                l0 += sacc[ni][0] + sacc[ni][1];
                l1 += sacc[ni][2] + sacc[ni][3];
            }

            // ---- O += P @ V (P relayout C-frag -> A-frag via shuffles) ----
#pragma unroll
            for (int kc = 0; kc < 8; kc++) {
                float v00 = __shfl_sync(0xffffffffu, sacc[kc][0], srcA);
                float v01 = __shfl_sync(0xffffffffu, sacc[kc][1], srcA);
                float v10 = __shfl_sync(0xffffffffu, sacc[kc][2], srcA);
                float v11 = __shfl_sync(0xffffffffu, sacc[kc][3], srcA);
                float w00 = __shfl_sync(0xffffffffu, sacc[kc][0], srcA + 2);
                float w01 = __shfl_sync(0xffffffffu, sacc[kc][1], srcA + 2);
                float w10 = __shfl_sync(0xffffffffu, sacc[kc][2], srcA + 2);
                float w11 = __shfl_sync(0xffffffffu, sacc[kc][3], srcA + 2);
                uint32_t a0 = f2tf32(odd ? v01 : v00);
                uint32_t a1 = f2tf32(odd ? v11 : v10);
                uint32_t a2 = f2tf32(odd ? w01 : w00);
                uint32_t a3 = f2tf32(odd ? w11 : w10);
#pragma unroll
                for (int ni = 0; ni < 8; ni++) {
                    uint32_t b0 = __float_as_uint(Vs[kc * 8 + t][ni * 8 + g]);
                    uint32_t b1 = __float_as_uint(Vs[kc * 8 + t + 4][ni * 8 + g]);
                    mma_tf32(oacc[ni][0], oacc[ni][1], oacc[ni][2], oacc[ni][3],
                             a0, a1, a2, a3, b0, b1);
                }
            }
        }
        __syncthreads();
    }

    // ---- epilogue ----
    l0 += __shfl_xor_sync(0xffffffffu, l0, 1);
    l0 += __shfl_xor_sync(0xffffffffu, l0, 2);
    l1 += __shfl_xor_sync(0xffffffffu, l1, 1);
    l1 += __shfl_xor_sync(0xffffffffu, l1, 2);
    float inv0 = 1.f / l0, inv1 = 1.f / l1;

    int R0 = rowBase + g;
    float* o0 = O + (size_t)(b * TT + R0) * DD + h * DH;
    float* o1 = o0 + (size_t)8 * DD;
#pragma unroll
    for (int ni = 0; ni < 8; ni++) {
        *(float2*)(o0 + ni * 8 + 2 * t) =
            make_float2(oacc[ni][0] * inv0, oacc[ni][1] * inv0);
        *(float2*)(o1 + ni * 8 + 2 * t) =
            make_float2(oacc[ni][2] * inv1, oacc[ni][3] * inv1);
    }
}

// ---------------------------------------------------------------------------
// Launch
// ---------------------------------------------------------------------------
extern "C" void kernel_launch(void* const* d_in, const int* in_sizes, int n_in,
                              void* d_out, int out_size)
{
    const float* x  = (const float*)d_in[0];
    const float* Wq = (const float*)d_in[1];
    const float* Wk = (const float*)d_in[2];
    const float* Wv = (const float*)d_in[3];
    const float* Wo = (const float*)d_in[4];
    float* out = (float*)d_out;

    float *q, *k, *v, *ctx;
    cudaGetSymbolAddress((void**)&q,   g_q);
    cudaGetSymbolAddress((void**)&k,   g_k);
    cudaGetSymbolAddress((void**)&v,   g_v);
    cudaGetSymbolAddress((void**)&ctx, g_ctx);

    const int M = BB * TT;   // 4096

    // Projections (tf32 tensor cores)
    gemm_tf32<<<dim3(DD / GBN, M / GBM), 256>>>(M, DD, DD, x, Wq, q);
    gemm_tf32<<<dim3((NKV * DH) / GBN, M / GBM), 256>>>(M, NKV * DH, DD, x, Wk, k);
    gemm_tf32<<<dim3((NKV * DH) / GBN, M / GBM), 256>>>(M, NKV * DH, DD, x, Wv, v);

    // RoPE (in place)
    {
        int totq = M * NH * 32;
        rope_kernel<<<(totq + 255) / 256, 256>>>(q, NH, totq);
        int totk = M * NKV * 32;
        rope_kernel<<<(totk + 255) / 256, 256>>>(k, NKV, totk);
    }

    // Attention (tensor cores)
    flash_attn_tc<<<dim3(TT / 128, NH, BB), 256>>>(q, k, v, ctx);

    // Output projection
    gemm_tf32<<<dim3(DD / GBN, M / GBM), 256>>>(M, DD, DD, ctx, Wo, out);
}

// round 4
// speedup vs baseline: 4.0972x; 1.2318x over previous
#include <cuda_runtime.h>
#include <math.h>
#include <stdint.h>

// Problem constants
#define BB 2
#define TT 2048
#define DD 2048
#define NH 32
#define NKV 8
#define DH 64
#define GG 4   // NH / NKV

// Scratch (device globals: no allocation allowed)
__device__ float g_q[BB * TT * DD];
__device__ float g_k[BB * TT * NKV * DH];
__device__ float g_v[BB * TT * NKV * DH];
__device__ float g_ctx[BB * TT * DD];
__device__ float2 g_trig[TT * 32];             // (cos, sin) per (t, i)

__device__ __forceinline__ uint32_t f2tf32(float f) {
    uint32_t u;
    asm("cvt.rna.tf32.f32 %0, %1;" : "=r"(u) : "f"(f));
    return u;
}

__device__ __forceinline__ void mma_tf32(
    float& d0, float& d1, float& d2, float& d3,
    uint32_t a0, uint32_t a1, uint32_t a2, uint32_t a3,
    uint32_t b0, uint32_t b1)
{
    asm volatile(
        "mma.sync.aligned.m16n8k8.row.col.f32.tf32.tf32.f32 "
        "{%0,%1,%2,%3}, {%4,%5,%6,%7}, {%8,%9}, {%0,%1,%2,%3};"
        : "+f"(d0), "+f"(d1), "+f"(d2), "+f"(d3)
        : "r"(a0), "r"(a1), "r"(a2), "r"(a3), "r"(b0), "r"(b1));
}

// ---------------------------------------------------------------------------
// TF32 GEMM, register-prefetch double-buffered. C = A @ B, row-major fp32.
// 128x128 tile, BK=16, 256 threads, warp tile 64x32.
// ---------------------------------------------------------------------------
#define GBM 128
#define GBN 128
#define GBK 16
#define GSTRIDE 136

__global__ __launch_bounds__(256, 2) void gemm_tf32(
    int M, int N, int K,
    const float* __restrict__ A, const float* __restrict__ B,
    float* __restrict__ C)
{
    __shared__ uint32_t As[2][GBK][GSTRIDE];
    __shared__ uint32_t Bs[2][GBK][GSTRIDE];

    const int tid = threadIdx.x;
    const int lane = tid & 31;
    const int warp = tid >> 5;
    const int g = lane >> 2;
    const int t = lane & 3;
    const int warpRow = warp & 1;
    const int warpCol = warp >> 1;

    const int rowBase = blockIdx.y * GBM;
    const int colBase = blockIdx.x * GBN;

    // per-thread load coordinates
    const int aRow0 = tid >> 1;                  // with second at +... (2 loads)
    // A tile: 128 rows x 16 cols = 512 float4; thread i handles idx=tid, tid+256
    // B tile: 16 rows x 128 cols = 512 float4; same split

    float4 aReg[2], bReg[2];

    // prefetch tile 0
#pragma unroll
    for (int i = 0; i < 2; i++) {
        int idx = tid + i * 256;
        int row = idx >> 2;
        int c4 = (idx & 3) * 4;
        aReg[i] = *(const float4*)(A + (size_t)(rowBase + row) * K + c4);
        int brow = idx >> 5;
        int bc4 = (idx & 31) * 4;
        bReg[i] = *(const float4*)(B + (size_t)brow * N + colBase + bc4);
    }

    float acc[4][4][4];
#pragma unroll
    for (int mi = 0; mi < 4; mi++)
#pragma unroll
        for (int ni = 0; ni < 4; ni++)
#pragma unroll
            for (int r = 0; r < 4; r++) acc[mi][ni][r] = 0.f;

    int cur = 0;
    for (int k0 = 0; k0 < K; k0 += GBK) {
        // store prefetched tile (cvt to tf32)
#pragma unroll
        for (int i = 0; i < 2; i++) {
            int idx = tid + i * 256;
            int row = idx >> 2;
            int c4 = (idx & 3) * 4;
            As[cur][c4 + 0][row] = f2tf32(aReg[i].x);
            As[cur][c4 + 1][row] = f2tf32(aReg[i].y);
            As[cur][c4 + 2][row] = f2tf32(aReg[i].z);
            As[cur][c4 + 3][row] = f2tf32(aReg[i].w);
            int brow = idx >> 5;
            int bc4 = (idx & 31) * 4;
            uint4 u;
            u.x = f2tf32(bReg[i].x); u.y = f2tf32(bReg[i].y);
            u.z = f2tf32(bReg[i].z); u.w = f2tf32(bReg[i].w);
            *(uint4*)&Bs[cur][brow][bc4] = u;
        }
        __syncthreads();

        // prefetch next tile
        if (k0 + GBK < K) {
#pragma unroll
            for (int i = 0; i < 2; i++) {
                int idx = tid + i * 256;
                int row = idx >> 2;
                int c4 = (idx & 3) * 4;
                aReg[i] = *(const float4*)(A + (size_t)(rowBase + row) * K + k0 + GBK + c4);
                int brow = idx >> 5;
                int bc4 = (idx & 31) * 4;
                bReg[i] = *(const float4*)(B + (size_t)(k0 + GBK + brow) * N + colBase + bc4);
            }
        }

        // compute
#pragma unroll
        for (int ks = 0; ks < GBK; ks += 8) {
            uint32_t af[4][4];
            uint32_t bf[4][2];
#pragma unroll
            for (int mi = 0; mi < 4; mi++) {
                int rb = warpRow * 64 + mi * 16;
                af[mi][0] = As[cur][ks + t][rb + g];
                af[mi][1] = As[cur][ks + t][rb + g + 8];
                af[mi][2] = As[cur][ks + t + 4][rb + g];
                af[mi][3] = As[cur][ks + t + 4][rb + g + 8];
            }
#pragma unroll
            for (int ni = 0; ni < 4; ni++) {
                int cb = warpCol * 32 + ni * 8 + g;
                bf[ni][0] = Bs[cur][ks + t][cb];
                bf[ni][1] = Bs[cur][ks + t + 4][cb];
            }
#pragma unroll
            for (int mi = 0; mi < 4; mi++)
#pragma unroll
                for (int ni = 0; ni < 4; ni++)
                    mma_tf32(acc[mi][ni][0], acc[mi][ni][1],
                             acc[mi][ni][2], acc[mi][ni][3],
                             af[mi][0], af[mi][1], af[mi][2], af[mi][3],
                             bf[ni][0], bf[ni][1]);
        }
        cur ^= 1;
    }

#pragma unroll
    for (int mi = 0; mi < 4; mi++) {
#pragma unroll
        for (int ni = 0; ni < 4; ni++) {
            int r0 = rowBase + warpRow * 64 + mi * 16 + g;
            int col = colBase + warpCol * 32 + ni * 8 + 2 * t;
            *(float2*)(C + (size_t)r0 * N + col) =
                make_float2(acc[mi][ni][0], acc[mi][ni][1]);
            *(float2*)(C + (size_t)(r0 + 8) * N + col) =
                make_float2(acc[mi][ni][2], acc[mi][ni][3]);
        }
    }
}

// ---------------------------------------------------------------------------
// Trig table init: g_trig[t*32+i] = (cos, sin) of t * 10000^(-i/32)
// ---------------------------------------------------------------------------
__global__ void trig_init()
{
    int idx = blockIdx.x * blockDim.x + threadIdx.x;
    if (idx >= TT * 32) return;
    int t = idx >> 5;
    int i = idx & 31;
    double inv = exp(-(double)i * (9.210340371976184 / 32.0));
    float ang = (float)t * (float)inv;
    float c, s;
    sincosf(ang, &s, &c);
    g_trig[idx] = make_float2(c, s);
}

// ---------------------------------------------------------------------------
// RoPE in-place, table-driven, vectorized. One thread per (n, h, i4-chunk).
// ---------------------------------------------------------------------------
__global__ void rope_kernel(float* __restrict__ X, int nheads, int total)
{
    int idx = blockIdx.x * blockDim.x + threadIdx.x;
    if (idx >= total) return;
    int i4 = (idx & 7) * 4;
    int hn = idx >> 3;
    int h = hn % nheads;
    int n = hn / nheads;
    int t = n & (TT - 1);

    const float2* tr = g_trig + t * 32 + i4;
    float2 t0 = tr[0], t1 = tr[1], t2 = tr[2], t3 = tr[3];

    float* p = X + (size_t)n * nheads * 64 + h * 64 + i4;
    float4 x1 = *(float4*)p;
    float4 x2 = *(float4*)(p + 32);

    float4 y1, y2;
    y1.x = x1.x * t0.x - x2.x * t0.y;  y2.x = x2.x * t0.x + x1.x * t0.y;
    y1.y = x1.y * t1.x - x2.y * t1.y;  y2.y = x2.y * t1.x + x1.y * t1.y;
    y1.z = x1.z * t2.x - x2.z * t2.y;  y2.z = x2.z * t2.x + x1.z * t2.y;
    y1.w = x1.w * t3.x - x2.w * t3.y;  y2.w = x2.w * t3.x + x1.w * t3.y;
    *(float4*)p = y1;
    *(float4*)(p + 32) = y2;
}

// ---------------------------------------------------------------------------
// Tensor-core flash attention (causal, GQA), double-buffered K/V.
// Dynamic SMEM: 2 buffers x (Ks 64x68 + Vs 64x72) floats.
// ---------------------------------------------------------------------------
#define KV_BUF_FLOATS 8960   // 64*68 + 64*72
#define KS_OFF 0
#define VS_OFF 4352          // 64*68

__global__ __launch_bounds__(256) void flash_attn_tc(
    const float* __restrict__ Q, const float* __restrict__ K,
    const float* __restrict__ V, float* __restrict__ O)
{
    extern __shared__ float sm[];

    const int tid = threadIdx.x;
    const int lane = tid & 31;
    const int warp = tid >> 5;
    const int g = lane >> 2;
    const int t = lane & 3;
    const int qt = blockIdx.x;
    const int h  = blockIdx.y;
    const int b  = blockIdx.z;
    const int kh = h / GG;
    const int rowBase = qt * 128 + warp * 16;

    const int kend = (qt + 1) * 128;

    // prefetch KV tile 0 into registers
    float4 kreg[4], vreg[4];
#pragma unroll
    for (int i = 0; i < 4; i++) {
        int lin = tid + i * 256;
        int r = lin >> 4;
        int c4 = (lin & 15) * 4;
        size_t base = (size_t)(b * TT + r) * (NKV * DH) + kh * DH + c4;
        kreg[i] = *(const float4*)(K + base);
        vreg[i] = *(const float4*)(V + base);
    }

    // ---- stage Q through buffer-0 V region, extract A fragments ----
    uint32_t qa[8][4];
    {
        float (*Qs)[72] = (float(*)[72])(sm + VS_OFF);
#pragma unroll
        for (int half = 0; half < 2; half++) {
#pragma unroll
            for (int i = 0; i < 4; i++) {
                int lin = tid + i * 256;
                int r = lin >> 4;
                int c4 = (lin & 15) * 4;
                const float* src = Q + (size_t)(b * TT + qt * 128 + half * 64 + r) * DD
                                     + h * DH + c4;
                *(float4*)&Qs[r][c4] = *(const float4*)src;
            }
            __syncthreads();
            if ((warp >> 2) == half) {
                int lr = (warp & 3) * 16 + g;
#pragma unroll
                for (int kc = 0; kc < 8; kc++) {
                    qa[kc][0] = f2tf32(Qs[lr][kc * 8 + t] * 0.125f);
                    qa[kc][1] = f2tf32(Qs[lr + 8][kc * 8 + t] * 0.125f);
                    qa[kc][2] = f2tf32(Qs[lr][kc * 8 + t + 4] * 0.125f);
                    qa[kc][3] = f2tf32(Qs[lr + 8][kc * 8 + t + 4] * 0.125f);
                }
            }
            __syncthreads();
        }
    }

    float oacc[8][4];
#pragma unroll
    for (int ni = 0; ni < 8; ni++)
#pragma unroll
        for (int r = 0; r < 4; r++) oacc[ni][r] = 0.f;
    float m0 = -1e30f, m1 = -1e30f, l0 = 0.f, l1 = 0.f;

    const int srcA = (lane & 28) | (t >> 1);
    const bool odd = (t & 1);

    int cur = 0;
    for (int s0 = 0; s0 < kend; s0 += 64) {
        float (*Ks)[68] = (float(*)[68])(sm + cur * KV_BUF_FLOATS + KS_OFF);
        float (*Vs)[72] = (float(*)[72])(sm + cur * KV_BUF_FLOATS + VS_OFF);

        // store prefetched tile with tf32 rounding
#pragma unroll
        for (int i = 0; i < 4; i++) {
            int lin = tid + i * 256;
            int r = lin >> 4;
            int c4 = (lin & 15) * 4;
            Ks[r][c4 + 0] = __uint_as_float(f2tf32(kreg[i].x));
            Ks[r][c4 + 1] = __uint_as_float(f2tf32(kreg[i].y));
            Ks[r][c4 + 2] = __uint_as_float(f2tf32(kreg[i].z));
            Ks[r][c4 + 3] = __uint_as_float(f2tf32(kreg[i].w));
            Vs[r][c4 + 0] = __uint_as_float(f2tf32(vreg[i].x));
            Vs[r][c4 + 1] = __uint_as_float(f2tf32(vreg[i].y));
            Vs[r][c4 + 2] = __uint_as_float(f2tf32(vreg[i].z));
            Vs[r][c4 + 3] = __uint_as_float(f2tf32(vreg[i].w));
        }
        __syncthreads();

        // prefetch next tile
        if (s0 + 64 < kend) {
#pragma unroll
            for (int i = 0; i < 4; i++) {
                int lin = tid + i * 256;
                int r = lin >> 4;
                int c4 = (lin & 15) * 4;
                size_t base = (size_t)(b * TT + s0 + 64 + r) * (NKV * DH) + kh * DH + c4;
                kreg[i] = *(const float4*)(K + base);
                vreg[i] = *(const float4*)(V + base);
            }
        }

        if (s0 <= rowBase + 15) {
            // ---- S = Q @ K^T ----
            float sacc[8][4];
#pragma unroll
            for (int ni = 0; ni < 8; ni++) {
                sacc[ni][0] = 0.f; sacc[ni][1] = 0.f;
                sacc[ni][2] = 0.f; sacc[ni][3] = 0.f;
#pragma unroll
                for (int kc = 0; kc < 8; kc++) {
                    uint32_t b0 = __float_as_uint(Ks[ni * 8 + g][kc * 8 + t]);
                    uint32_t b1 = __float_as_uint(Ks[ni * 8 + g][kc * 8 + t + 4]);
                    mma_tf32(sacc[ni][0], sacc[ni][1], sacc[ni][2], sacc[ni][3],
                             qa[kc][0], qa[kc][1], qa[kc][2], qa[kc][3], b0, b1);
                }
            }

            // ---- causal mask ----
            if (s0 + 63 > rowBase) {
                int r0 = rowBase + g;
                int r1 = r0 + 8;
#pragma unroll
                for (int ni = 0; ni < 8; ni++) {
                    int c = s0 + ni * 8 + 2 * t;
                    if (c > r0)     sacc[ni][0] = -1e30f;
                    if (c + 1 > r0) sacc[ni][1] = -1e30f;
                    if (c > r1)     sacc[ni][2] = -1e30f;
                    if (c + 1 > r1) sacc[ni][3] = -1e30f;
                }
            }

            // ---- online softmax ----
            float mx0 = -1e30f, mx1 = -1e30f;
#pragma unroll
            for (int ni = 0; ni < 8; ni++) {
                mx0 = fmaxf(mx0, fmaxf(sacc[ni][0], sacc[ni][1]));
                mx1 = fmaxf(mx1, fmaxf(sacc[ni][2], sacc[ni][3]));
            }
            mx0 = fmaxf(mx0, __shfl_xor_sync(0xffffffffu, mx0, 1));
            mx0 = fmaxf(mx0, __shfl_xor_sync(0xffffffffu, mx0, 2));
            mx1 = fmaxf(mx1, __shfl_xor_sync(0xffffffffu, mx1, 1));
            mx1 = fmaxf(mx1, __shfl_xor_sync(0xffffffffu, mx1, 2));

            float mn0 = fmaxf(m0, mx0), mn1 = fmaxf(m1, mx1);
            float cr0 = __expf(m0 - mn0), cr1 = __expf(m1 - mn1);
            m0 = mn0; m1 = mn1;
            l0 *= cr0; l1 *= cr1;
#pragma unroll
            for (int ni = 0; ni < 8; ni++) {
                oacc[ni][0] *= cr0; oacc[ni][1] *= cr0;
                oacc[ni][2] *= cr1; oacc[ni][3] *= cr1;
            }
#pragma unroll
            for (int ni = 0; ni < 8; ni++) {
                sacc[ni][0] = __expf(sacc[ni][0] - m0);
                sacc[ni][1] = __expf(sacc[ni][1] - m0);
                sacc[ni][2] = __expf(sacc[ni][2] - m1);
                sacc[ni][3] = __expf(sacc[ni][3] - m1);
                l0 += sacc[ni][0] + sacc[ni][1];
                l1 += sacc[ni][2] + sacc[ni][3];
            }

            // ---- O += P @ V ----
#pragma unroll
            for (int kc = 0; kc < 8; kc++) {
                float v00 = __shfl_sync(0xffffffffu, sacc[kc][0], srcA);
                float v01 = __shfl_sync(0xffffffffu, sacc[kc][1], srcA);
                float v10 = __shfl_sync(0xffffffffu, sacc[kc][2], srcA);
                float v11 = __shfl_sync(0xffffffffu, sacc[kc][3], srcA);
                float w00 = __shfl_sync(0xffffffffu, sacc[kc][0], srcA + 2);
                float w01 = __shfl_sync(0xffffffffu, sacc[kc][1], srcA + 2);
                float w10 = __shfl_sync(0xffffffffu, sacc[kc][2], srcA + 2);
                float w11 = __shfl_sync(0xffffffffu, sacc[kc][3], srcA + 2);
                uint32_t a0 = f2tf32(odd ? v01 : v00);
                uint32_t a1 = f2tf32(odd ? v11 : v10);
                uint32_t a2 = f2tf32(odd ? w01 : w00);
                uint32_t a3 = f2tf32(odd ? w11 : w10);
#pragma unroll
                for (int ni = 0; ni < 8; ni++) {
                    uint32_t b0 = __float_as_uint(Vs[kc * 8 + t][ni * 8 + g]);
                    uint32_t b1 = __float_as_uint(Vs[kc * 8 + t + 4][ni * 8 + g]);
                    mma_tf32(oacc[ni][0], oacc[ni][1], oacc[ni][2], oacc[ni][3],
                             a0, a1, a2, a3, b0, b1);
                }
            }
        }
        cur ^= 1;
    }

    // ---- epilogue ----
    l0 += __shfl_xor_sync(0xffffffffu, l0, 1);
    l0 += __shfl_xor_sync(0xffffffffu, l0, 2);
    l1 += __shfl_xor_sync(0xffffffffu, l1, 1);
    l1 += __shfl_xor_sync(0xffffffffu, l1, 2);
    float inv0 = 1.f / l0, inv1 = 1.f / l1;

    int R0 = rowBase + g;
    float* o0 = O + (size_t)(b * TT + R0) * DD + h * DH;
    float* o1 = o0 + (size_t)8 * DD;
#pragma unroll
    for (int ni = 0; ni < 8; ni++) {
        *(float2*)(o0 + ni * 8 + 2 * t) =
            make_float2(oacc[ni][0] * inv0, oacc[ni][1] * inv0);
        *(float2*)(o1 + ni * 8 + 2 * t) =
            make_float2(oacc[ni][2] * inv1, oacc[ni][3] * inv1);
    }
}

// ---------------------------------------------------------------------------
// Launch
// ---------------------------------------------------------------------------
extern "C" void kernel_launch(void* const* d_in, const int* in_sizes, int n_in,
                              void* d_out, int out_size)
{
    const float* x  = (const float*)d_in[0];
    const float* Wq = (const float*)d_in[1];
    const float* Wk = (const float*)d_in[2];
    const float* Wv = (const float*)d_in[3];
    const float* Wo = (const float*)d_in[4];
    float* out = (float*)d_out;

    float *q, *k, *v, *ctx;
    cudaGetSymbolAddress((void**)&q,   g_q);
    cudaGetSymbolAddress((void**)&k,   g_k);
    cudaGetSymbolAddress((void**)&v,   g_v);
    cudaGetSymbolAddress((void**)&ctx, g_ctx);

    static bool attr_set = false;
    if (!attr_set) {
        cudaFuncSetAttribute(flash_attn_tc,
                             cudaFuncAttributeMaxDynamicSharedMemorySize,
                             2 * KV_BUF_FLOATS * (int)sizeof(float));
        attr_set = true;
    }

    const int M = BB * TT;   // 4096

    // trig table (deterministic each call)
    trig_init<<<(TT * 32 + 255) / 256, 256>>>();

    // Projections (tf32 tensor cores, double-buffered)
    gemm_tf32<<<dim3(DD / GBN, M / GBM), 256>>>(M, DD, DD, x, Wq, q);
    gemm_tf32<<<dim3((NKV * DH) / GBN, M / GBM), 256>>>(M, NKV * DH, DD, x, Wk, k);
    gemm_tf32<<<dim3((NKV * DH) / GBN, M / GBM), 256>>>(M, NKV * DH, DD, x, Wv, v);

    // RoPE (table-driven)
    {
        int totq = M * NH * 8;
        rope_kernel<<<(totq + 255) / 256, 256>>>(q, NH, totq);
        int totk = M * NKV * 8;
        rope_kernel<<<(totk + 255) / 256, 256>>>(k, NKV, totk);
    }

    // Attention (tensor cores, double-buffered)
    flash_attn_tc<<<dim3(TT / 128, NH, BB), 256,
                    2 * KV_BUF_FLOATS * sizeof(float)>>>(q, k, v, ctx);

    // Output projection
    gemm_tf32<<<dim3(DD / GBN, M / GBM), 256>>>(M, DD, DD, ctx, Wo, out);
}

// round 5
// speedup vs baseline: 4.4179x; 1.0783x over previous
#include <cuda_runtime.h>
#include <math.h>
#include <stdint.h>

// Problem constants
#define BB 2
#define TT 2048
#define DD 2048
#define NH 32
#define NKV 8
#define DH 64
#define GG 4   // NH / NKV

// Scratch (device globals: no allocation allowed)
__device__ float g_q[BB * TT * DD];
__device__ float g_k[BB * TT * NKV * DH];
__device__ float g_v[BB * TT * NKV * DH];
__device__ float g_ctx[BB * TT * DD];
__device__ float2 g_trig[TT * 32];             // (cos, sin) per (t, i)

__device__ __forceinline__ uint32_t f2tf32(float f) {
    uint32_t u;
    asm("cvt.rna.tf32.f32 %0, %1;" : "=r"(u) : "f"(f));
    return u;
}

__device__ __forceinline__ void mma_tf32(
    float& d0, float& d1, float& d2, float& d3,
    uint32_t a0, uint32_t a1, uint32_t a2, uint32_t a3,
    uint32_t b0, uint32_t b1)
{
    asm volatile(
        "mma.sync.aligned.m16n8k8.row.col.f32.tf32.tf32.f32 "
        "{%0,%1,%2,%3}, {%4,%5,%6,%7}, {%8,%9}, {%0,%1,%2,%3};"
        : "+f"(d0), "+f"(d1), "+f"(d2), "+f"(d3)
        : "r"(a0), "r"(a1), "r"(a2), "r"(a3), "r"(b0), "r"(b1));
}

// ---------------------------------------------------------------------------
// Core tf32 GEMM body (register-prefetch double-buffered), parameterized by
// A/B/C pointers and N stride. 128x128 tile, BK=16, 256 threads.
// ---------------------------------------------------------------------------
#define GBM 128
#define GBN 128
#define GBK 16
#define GSTRIDE 136

__device__ __forceinline__ void gemm_body(
    int N, int K,
    const float* __restrict__ A, const float* __restrict__ B,
    float* __restrict__ C, int rowBase, int colBase,
    uint32_t (*As)[GBK][GSTRIDE], uint32_t (*Bs)[GBK][GSTRIDE])
{
    const int tid = threadIdx.x;
    const int lane = tid & 31;
    const int warp = tid >> 5;
    const int g = lane >> 2;
    const int t = lane & 3;
    const int warpRow = warp & 1;
    const int warpCol = warp >> 1;

    float4 aReg[2], bReg[2];
#pragma unroll
    for (int i = 0; i < 2; i++) {
        int idx = tid + i * 256;
        int row = idx >> 2;
        int c4 = (idx & 3) * 4;
        aReg[i] = *(const float4*)(A + (size_t)(rowBase + row) * K + c4);
        int brow = idx >> 5;
        int bc4 = (idx & 31) * 4;
        bReg[i] = *(const float4*)(B + (size_t)brow * N + colBase + bc4);
    }

    float acc[4][4][4];
#pragma unroll
    for (int mi = 0; mi < 4; mi++)
#pragma unroll
        for (int ni = 0; ni < 4; ni++)
#pragma unroll
            for (int r = 0; r < 4; r++) acc[mi][ni][r] = 0.f;

    int cur = 0;
    for (int k0 = 0; k0 < K; k0 += GBK) {
#pragma unroll
        for (int i = 0; i < 2; i++) {
            int idx = tid + i * 256;
            int row = idx >> 2;
            int c4 = (idx & 3) * 4;
            As[cur][c4 + 0][row] = f2tf32(aReg[i].x);
            As[cur][c4 + 1][row] = f2tf32(aReg[i].y);
            As[cur][c4 + 2][row] = f2tf32(aReg[i].z);
            As[cur][c4 + 3][row] = f2tf32(aReg[i].w);
            int brow = idx >> 5;
            int bc4 = (idx & 31) * 4;
            uint4 u;
            u.x = f2tf32(bReg[i].x); u.y = f2tf32(bReg[i].y);
            u.z = f2tf32(bReg[i].z); u.w = f2tf32(bReg[i].w);
            *(uint4*)&Bs[cur][brow][bc4] = u;
        }
        __syncthreads();

        if (k0 + GBK < K) {
#pragma unroll
            for (int i = 0; i < 2; i++) {
                int idx = tid + i * 256;
                int row = idx >> 2;
                int c4 = (idx & 3) * 4;
                aReg[i] = *(const float4*)(A + (size_t)(rowBase + row) * K + k0 + GBK + c4);
                int brow = idx >> 5;
                int bc4 = (idx & 31) * 4;
                bReg[i] = *(const float4*)(B + (size_t)(k0 + GBK + brow) * N + colBase + bc4);
            }
        }

#pragma unroll
        for (int ks = 0; ks < GBK; ks += 8) {
            uint32_t af[4][4];
            uint32_t bf[4][2];
#pragma unroll
            for (int mi = 0; mi < 4; mi++) {
                int rb = warpRow * 64 + mi * 16;
                af[mi][0] = As[cur][ks + t][rb + g];
                af[mi][1] = As[cur][ks + t][rb + g + 8];
                af[mi][2] = As[cur][ks + t + 4][rb + g];
                af[mi][3] = As[cur][ks + t + 4][rb + g + 8];
            }
#pragma unroll
            for (int ni = 0; ni < 4; ni++) {
                int cb = warpCol * 32 + ni * 8 + g;
                bf[ni][0] = Bs[cur][ks + t][cb];
                bf[ni][1] = Bs[cur][ks + t + 4][cb];
            }
#pragma unroll
            for (int mi = 0; mi < 4; mi++)
#pragma unroll
                for (int ni = 0; ni < 4; ni++)
                    mma_tf32(acc[mi][ni][0], acc[mi][ni][1],
                             acc[mi][ni][2], acc[mi][ni][3],
                             af[mi][0], af[mi][1], af[mi][2], af[mi][3],
                             bf[ni][0], bf[ni][1]);
        }
        cur ^= 1;
    }

#pragma unroll
    for (int mi = 0; mi < 4; mi++) {
#pragma unroll
        for (int ni = 0; ni < 4; ni++) {
            int r0 = rowBase + warpRow * 64 + mi * 16 + g;
            int col = colBase + warpCol * 32 + ni * 8 + 2 * t;
            *(float2*)(C + (size_t)r0 * N + col) =
                make_float2(acc[mi][ni][0], acc[mi][ni][1]);
            *(float2*)(C + (size_t)(r0 + 8) * N + col) =
                make_float2(acc[mi][ni][2], acc[mi][ni][3]);
        }
    }
}

// Generic GEMM (used for output projection)
__global__ __launch_bounds__(256, 2) void gemm_tf32(
    int M, int N, int K,
    const float* __restrict__ A, const float* __restrict__ B,
    float* __restrict__ C)
{
    __shared__ uint32_t As[2][GBK][GSTRIDE];
    __shared__ uint32_t Bs[2][GBK][GSTRIDE];
    gemm_body(N, K, A, B, C, blockIdx.y * GBM, blockIdx.x * GBN, As, Bs);
}

// Fused QKV projection: blockIdx.x in [0,24): 0-15 -> Wq, 16-19 -> Wk, 20-23 -> Wv
__global__ __launch_bounds__(256, 2) void gemm_qkv(
    const float* __restrict__ X,
    const float* __restrict__ Wq, const float* __restrict__ Wk,
    const float* __restrict__ Wv,
    float* __restrict__ Qo, float* __restrict__ Ko, float* __restrict__ Vo)
{
    __shared__ uint32_t As[2][GBK][GSTRIDE];
    __shared__ uint32_t Bs[2][GBK][GSTRIDE];

    int bx = blockIdx.x;
    const float* B;
    float* C;
    int N, colBase;
    if (bx < 16)      { B = Wq; C = Qo; N = DD;        colBase = bx * 128; }
    else if (bx < 20) { B = Wk; C = Ko; N = NKV * DH;  colBase = (bx - 16) * 128; }
    else              { B = Wv; C = Vo; N = NKV * DH;  colBase = (bx - 20) * 128; }

    gemm_body(N, DD, X, B, C, blockIdx.y * GBM, colBase, As, Bs);
}

// ---------------------------------------------------------------------------
// Trig table init
// ---------------------------------------------------------------------------
__global__ void trig_init()
{
    int idx = blockIdx.x * blockDim.x + threadIdx.x;
    if (idx >= TT * 32) return;
    int t = idx >> 5;
    int i = idx & 31;
    double inv = exp(-(double)i * (9.210340371976184 / 32.0));
    float ang = (float)t * (float)inv;
    float c, s;
    sincosf(ang, &s, &c);
    g_trig[idx] = make_float2(c, s);
}

// ---------------------------------------------------------------------------
// RoPE for both q and k in one launch, table-driven, vectorized.
// ---------------------------------------------------------------------------
__device__ __forceinline__ void rope_apply(float* __restrict__ X, int nheads, int idx)
{
    int i4 = (idx & 7) * 4;
    int hn = idx >> 3;
    int h = hn % nheads;
    int n = hn / nheads;
    int t = n & (TT - 1);

    const float2* tr = g_trig + t * 32 + i4;
    float2 t0 = tr[0], t1 = tr[1], t2 = tr[2], t3 = tr[3];

    float* p = X + (size_t)n * nheads * 64 + h * 64 + i4;
    float4 x1 = *(float4*)p;
    float4 x2 = *(float4*)(p + 32);

    float4 y1, y2;
    y1.x = x1.x * t0.x - x2.x * t0.y;  y2.x = x2.x * t0.x + x1.x * t0.y;
    y1.y = x1.y * t1.x - x2.y * t1.y;  y2.y = x2.y * t1.x + x1.y * t1.y;
    y1.z = x1.z * t2.x - x2.z * t2.y;  y2.z = x2.z * t2.x + x1.z * t2.y;
    y1.w = x1.w * t3.x - x2.w * t3.y;  y2.w = x2.w * t3.x + x1.w * t3.y;
    *(float4*)p = y1;
    *(float4*)(p + 32) = y2;
}

__global__ void rope_both(float* __restrict__ Qx, float* __restrict__ Kx,
                          int totq, int totk)
{
    int idx = blockIdx.x * blockDim.x + threadIdx.x;
    if (idx < totq) rope_apply(Qx, NH, idx);
    else if (idx < totq + totk) rope_apply(Kx, NKV, idx - totq);
}

// ---------------------------------------------------------------------------
// Tensor-core flash attention (causal, GQA), double-buffered K/V.
// ---------------------------------------------------------------------------
#define KV_BUF_FLOATS 8960   // 64*68 + 64*72
#define KS_OFF 0
#define VS_OFF 4352          // 64*68

__global__ __launch_bounds__(256) void flash_attn_tc(
    const float* __restrict__ Q, const float* __restrict__ K,
    const float* __restrict__ V, float* __restrict__ O)
{
    extern __shared__ float sm[];

    const int tid = threadIdx.x;
    const int lane = tid & 31;
    const int warp = tid >> 5;
    const int g = lane >> 2;
    const int t = lane & 3;
    const int qt = blockIdx.x;
    const int h  = blockIdx.y;
    const int b  = blockIdx.z;
    const int kh = h / GG;
    const int rowBase = qt * 128 + warp * 16;

    const int kend = (qt + 1) * 128;

    float4 kreg[4], vreg[4];
#pragma unroll
    for (int i = 0; i < 4; i++) {
        int lin = tid + i * 256;
        int r = lin >> 4;
        int c4 = (lin & 15) * 4;
        size_t base = (size_t)(b * TT + r) * (NKV * DH) + kh * DH + c4;
        kreg[i] = *(const float4*)(K + base);
        vreg[i] = *(const float4*)(V + base);
    }

    uint32_t qa[8][4];
    {
        float (*Qs)[72] = (float(*)[72])(sm + VS_OFF);
#pragma unroll
        for (int half = 0; half < 2; half++) {
#pragma unroll
            for (int i = 0; i < 4; i++) {
                int lin = tid + i * 256;
                int r = lin >> 4;
                int c4 = (lin & 15) * 4;
                const float* src = Q + (size_t)(b * TT + qt * 128 + half * 64 + r) * DD
                                     + h * DH + c4;
                *(float4*)&Qs[r][c4] = *(const float4*)src;
            }
            __syncthreads();
            if ((warp >> 2) == half) {
                int lr = (warp & 3) * 16 + g;
#pragma unroll
                for (int kc = 0; kc < 8; kc++) {
                    qa[kc][0] = f2tf32(Qs[lr][kc * 8 + t] * 0.125f);
                    qa[kc][1] = f2tf32(Qs[lr + 8][kc * 8 + t] * 0.125f);
                    qa[kc][2] = f2tf32(Qs[lr][kc * 8 + t + 4] * 0.125f);
                    qa[kc][3] = f2tf32(Qs[lr + 8][kc * 8 + t + 4] * 0.125f);
                }
            }
            __syncthreads();
        }
    }

    float oacc[8][4];
#pragma unroll
    for (int ni = 0; ni < 8; ni++)
#pragma unroll
        for (int r = 0; r < 4; r++) oacc[ni][r] = 0.f;
    float m0 = -1e30f, m1 = -1e30f, l0 = 0.f, l1 = 0.f;

    const int srcA = (lane & 28) | (t >> 1);
    const bool odd = (t & 1);

    int cur = 0;
    for (int s0 = 0; s0 < kend; s0 += 64) {
        float (*Ks)[68] = (float(*)[68])(sm + cur * KV_BUF_FLOATS + KS_OFF);
        float (*Vs)[72] = (float(*)[72])(sm + cur * KV_BUF_FLOATS + VS_OFF);

#pragma unroll
        for (int i = 0; i < 4; i++) {
            int lin = tid + i * 256;
            int r = lin >> 4;
            int c4 = (lin & 15) * 4;
            Ks[r][c4 + 0] = __uint_as_float(f2tf32(kreg[i].x));
            Ks[r][c4 + 1] = __uint_as_float(f2tf32(kreg[i].y));
            Ks[r][c4 + 2] = __uint_as_float(f2tf32(kreg[i].z));
            Ks[r][c4 + 3] = __uint_as_float(f2tf32(kreg[i].w));
            Vs[r][c4 + 0] = __uint_as_float(f2tf32(vreg[i].x));
            Vs[r][c4 + 1] = __uint_as_float(f2tf32(vreg[i].y));
            Vs[r][c4 + 2] = __uint_as_float(f2tf32(vreg[i].z));
            Vs[r][c4 + 3] = __uint_as_float(f2tf32(vreg[i].w));
        }
        __syncthreads();

        if (s0 + 64 < kend) {
#pragma unroll
            for (int i = 0; i < 4; i++) {
                int lin = tid + i * 256;
                int r = lin >> 4;
                int c4 = (lin & 15) * 4;
                size_t base = (size_t)(b * TT + s0 + 64 + r) * (NKV * DH) + kh * DH + c4;
                kreg[i] = *(const float4*)(K + base);
                vreg[i] = *(const float4*)(V + base);
            }
        }

        if (s0 <= rowBase + 15) {
            float sacc[8][4];
#pragma unroll
            for (int ni = 0; ni < 8; ni++) {
                sacc[ni][0] = 0.f; sacc[ni][1] = 0.f;
                sacc[ni][2] = 0.f; sacc[ni][3] = 0.f;
#pragma unroll
                for (int kc = 0; kc < 8; kc++) {
                    uint32_t b0 = __float_as_uint(Ks[ni * 8 + g][kc * 8 + t]);
                    uint32_t b1 = __float_as_uint(Ks[ni * 8 + g][kc * 8 + t + 4]);
                    mma_tf32(sacc[ni][0], sacc[ni][1], sacc[ni][2], sacc[ni][3],
                             qa[kc][0], qa[kc][1], qa[kc][2], qa[kc][3], b0, b1);
                }
            }

            if (s0 + 63 > rowBase) {
                int r0 = rowBase + g;
                int r1 = r0 + 8;
#pragma unroll
                for (int ni = 0; ni < 8; ni++) {
                    int c = s0 + ni * 8 + 2 * t;
                    if (c > r0)     sacc[ni][0] = -1e30f;
                    if (c + 1 > r0) sacc[ni][1] = -1e30f;
                    if (c > r1)     sacc[ni][2] = -1e30f;
                    if (c + 1 > r1) sacc[ni][3] = -1e30f;
                }
            }

            float mx0 = -1e30f, mx1 = -1e30f;
#pragma unroll
            for (int ni = 0; ni < 8; ni++) {
                mx0 = fmaxf(mx0, fmaxf(sacc[ni][0], sacc[ni][1]));
                mx1 = fmaxf(mx1, fmaxf(sacc[ni][2], sacc[ni][3]));
            }
            mx0 = fmaxf(mx0, __shfl_xor_sync(0xffffffffu, mx0, 1));
            mx0 = fmaxf(mx0, __shfl_xor_sync(0xffffffffu, mx0, 2));
            mx1 = fmaxf(mx1, __shfl_xor_sync(0xffffffffu, mx1, 1));
            mx1 = fmaxf(mx1, __shfl_xor_sync(0xffffffffu, mx1, 2));

            float mn0 = fmaxf(m0, mx0), mn1 = fmaxf(m1, mx1);
            float cr0 = __expf(m0 - mn0), cr1 = __expf(m1 - mn1);
            m0 = mn0; m1 = mn1;
            l0 *= cr0; l1 *= cr1;
#pragma unroll
            for (int ni = 0; ni < 8; ni++) {
                oacc[ni][0] *= cr0; oacc[ni][1] *= cr0;
                oacc[ni][2] *= cr1; oacc[ni][3] *= cr1;
            }
#pragma unroll
            for (int ni = 0; ni < 8; ni++) {
                sacc[ni][0] = __expf(sacc[ni][0] - m0);
                sacc[ni][1] = __expf(sacc[ni][1] - m0);
                sacc[ni][2] = __expf(sacc[ni][2] - m1);
                sacc[ni][3] = __expf(sacc[ni][3] - m1);
                l0 += sacc[ni][0] + sacc[ni][1];
                l1 += sacc[ni][2] + sacc[ni][3];
            }

#pragma unroll
            for (int kc = 0; kc < 8; kc++) {
                float v00 = __shfl_sync(0xffffffffu, sacc[kc][0], srcA);
                float v01 = __shfl_sync(0xffffffffu, sacc[kc][1], srcA);
                float v10 = __shfl_sync(0xffffffffu, sacc[kc][2], srcA);
                float v11 = __shfl_sync(0xffffffffu, sacc[kc][3], srcA);
                float w00 = __shfl_sync(0xffffffffu, sacc[kc][0], srcA + 2);
                float w01 = __shfl_sync(0xffffffffu, sacc[kc][1], srcA + 2);
                float w10 = __shfl_sync(0xffffffffu, sacc[kc][2], srcA + 2);
                float w11 = __shfl_sync(0xffffffffu, sacc[kc][3], srcA + 2);
                uint32_t a0 = f2tf32(odd ? v01 : v00);
                uint32_t a1 = f2tf32(odd ? v11 : v10);
                uint32_t a2 = f2tf32(odd ? w01 : w00);
                uint32_t a3 = f2tf32(odd ? w11 : w10);
#pragma unroll
                for (int ni = 0; ni < 8; ni++) {
                    uint32_t b0 = __float_as_uint(Vs[kc * 8 + t][ni * 8 + g]);
                    uint32_t b1 = __float_as_uint(Vs[kc * 8 + t + 4][ni * 8 + g]);
                    mma_tf32(oacc[ni][0], oacc[ni][1], oacc[ni][2], oacc[ni][3],
                             a0, a1, a2, a3, b0, b1);
                }
            }
        }
        cur ^= 1;
    }

    l0 += __shfl_xor_sync(0xffffffffu, l0, 1);
    l0 += __shfl_xor_sync(0xffffffffu, l0, 2);
    l1 += __shfl_xor_sync(0xffffffffu, l1, 1);
    l1 += __shfl_xor_sync(0xffffffffu, l1, 2);
    float inv0 = 1.f / l0, inv1 = 1.f / l1;

    int R0 = rowBase + g;
    float* o0 = O + (size_t)(b * TT + R0) * DD + h * DH;
    float* o1 = o0 + (size_t)8 * DD;
#pragma unroll
    for (int ni = 0; ni < 8; ni++) {
        *(float2*)(o0 + ni * 8 + 2 * t) =
            make_float2(oacc[ni][0] * inv0, oacc[ni][1] * inv0);
        *(float2*)(o1 + ni * 8 + 2 * t) =
            make_float2(oacc[ni][2] * inv1, oacc[ni][3] * inv1);
    }
}

// ---------------------------------------------------------------------------
// Launch
// ---------------------------------------------------------------------------
extern "C" void kernel_launch(void* const* d_in, const int* in_sizes, int n_in,
                              void* d_out, int out_size)
{
    const float* x  = (const float*)d_in[0];
    const float* Wq = (const float*)d_in[1];
    const float* Wk = (const float*)d_in[2];
    const float* Wv = (const float*)d_in[3];
    const float* Wo = (const float*)d_in[4];
    float* out = (float*)d_out;

    float *q, *k, *v, *ctx;
    cudaGetSymbolAddress((void**)&q,   g_q);
    cudaGetSymbolAddress((void**)&k,   g_k);
    cudaGetSymbolAddress((void**)&v,   g_v);
    cudaGetSymbolAddress((void**)&ctx, g_ctx);

    static bool attr_set = false;
    if (!attr_set) {
        cudaFuncSetAttribute(flash_attn_tc,
                             cudaFuncAttributeMaxDynamicSharedMemorySize,
                             2 * KV_BUF_FLOATS * (int)sizeof(float));
        attr_set = true;
    }

    const int M = BB * TT;   // 4096

    trig_init<<<(TT * 32 + 255) / 256, 256>>>();

    // Fused QKV projection (24 block columns: 16 Q, 4 K, 4 V)
    gemm_qkv<<<dim3(24, M / GBM), 256>>>(x, Wq, Wk, Wv, q, k, v);

    // RoPE (q and k in one launch)
    {
        int totq = M * NH * 8;
        int totk = M * NKV * 8;
        rope_both<<<(totq + totk + 255) / 256, 256>>>(q, k, totq, totk);
    }

    // Attention (tensor cores, double-buffered)
    flash_attn_tc<<<dim3(TT / 128, NH, BB), 256,
                    2 * KV_BUF_FLOATS * sizeof(float)>>>(q, k, v, ctx);

    // Output projection
    gemm_tf32<<<dim3(DD / GBN, M / GBM), 256>>>(M, DD, DD, ctx, Wo, out);
}

// round 6
// speedup vs baseline: 5.0764x; 1.1491x over previous
#include <cuda_runtime.h>
#include <math.h>
#include <stdint.h>

// Problem constants
#define BB 2
#define TT 2048
#define DD 2048
#define NH 32
#define NKV 8
#define DH 64
#define GG 4   // NH / NKV

// Scratch (device globals: no allocation allowed)
__device__ float g_q[BB * TT * DD];
__device__ float g_k[BB * TT * NKV * DH];
__device__ float g_v[BB * TT * NKV * DH];
__device__ float g_ctx[BB * TT * DD];
__device__ float g_xr[BB * TT * DD];          // tf32-rounded copies
__device__ float g_wqr[DD * DD];
__device__ float g_wkr[DD * NKV * DH];
__device__ float g_wvr[DD * NKV * DH];
__device__ float g_wor[DD * DD];
__device__ float2 g_trig[TT * 32];

__device__ __forceinline__ uint32_t f2tf32(float f) {
    uint32_t u;
    asm("cvt.rna.tf32.f32 %0, %1;" : "=r"(u) : "f"(f));
    return u;
}
__device__ __forceinline__ float rtf(float f) {
    return __uint_as_float(f2tf32(f));
}

__device__ __forceinline__ void mma_tf32(
    float& d0, float& d1, float& d2, float& d3,
    uint32_t a0, uint32_t a1, uint32_t a2, uint32_t a3,
    uint32_t b0, uint32_t b1)
{
    asm volatile(
        "mma.sync.aligned.m16n8k8.row.col.f32.tf32.tf32.f32 "
        "{%0,%1,%2,%3}, {%4,%5,%6,%7}, {%8,%9}, {%0,%1,%2,%3};"
        : "+f"(d0), "+f"(d1), "+f"(d2), "+f"(d3)
        : "r"(a0), "r"(a1), "r"(a2), "r"(a3), "r"(b0), "r"(b1));
}

__device__ __forceinline__ void cp16(void* dst, const void* src) {
    uint32_t d = (uint32_t)__cvta_generic_to_shared(dst);
    asm volatile("cp.async.cg.shared.global [%0], [%1], 16;" :: "r"(d), "l"(src));
}
#define CP_COMMIT() asm volatile("cp.async.commit_group;")
#define CP_WAIT0()  asm volatile("cp.async.wait_group 0;" ::: "memory")

// ---------------------------------------------------------------------------
// Elementwise tf32 round-copy
// ---------------------------------------------------------------------------
__global__ void round_copy(const float4* __restrict__ src,
                           float4* __restrict__ dst, int n4)
{
    int i = blockIdx.x * blockDim.x + threadIdx.x;
    if (i >= n4) return;
    float4 a = src[i];
    float4 r;
    r.x = rtf(a.x); r.y = rtf(a.y); r.z = rtf(a.z); r.w = rtf(a.w);
    dst[i] = r;
}

// ---------------------------------------------------------------------------
// TF32 GEMM with cp.async double-buffering. Inputs MUST be tf32-rounded.
// C = A @ B, row-major. 128x128 tile, BK=16, 256 threads, warp tile 64x32.
// A smem: [128][20] (untransposed, pad 20), B smem: [16][136].
// ---------------------------------------------------------------------------
#define GBM 128
#define GBN 128
#define GBK 16
#define ASTRIDE 20
#define BSTRIDE 136

__device__ __forceinline__ void gemm_issue(
    const float* __restrict__ A, const float* __restrict__ B,
    int N, int K, int rowBase, int colBase, int k0,
    float (*As)[GBM][ASTRIDE], float (*Bs)[GBK][BSTRIDE], int buf, int tid)
{
#pragma unroll
    for (int i = 0; i < 2; i++) {
        int idx = tid + i * 256;
        int row = idx >> 2;
        int c4 = (idx & 3) * 4;
        cp16(&As[buf][row][c4], A + (size_t)(rowBase + row) * K + k0 + c4);
        int brow = idx >> 5;
        int bc4 = (idx & 31) * 4;
        cp16(&Bs[buf][brow][bc4], B + (size_t)(k0 + brow) * N + colBase + bc4);
    }
}

__device__ __forceinline__ void gemm_body(
    int N, int K,
    const float* __restrict__ A, const float* __restrict__ B,
    float* __restrict__ C, int rowBase, int colBase,
    float (*As)[GBM][ASTRIDE], float (*Bs)[GBK][BSTRIDE])
{
    const int tid = threadIdx.x;
    const int lane = tid & 31;
    const int warp = tid >> 5;
    const int g = lane >> 2;
    const int t = lane & 3;
    const int warpRow = warp & 1;
    const int warpCol = warp >> 1;

    gemm_issue(A, B, N, K, rowBase, colBase, 0, As, Bs, 0, tid);
    CP_COMMIT();

    float acc[4][4][4];
#pragma unroll
    for (int mi = 0; mi < 4; mi++)
#pragma unroll
        for (int ni = 0; ni < 4; ni++)
#pragma unroll
            for (int r = 0; r < 4; r++) acc[mi][ni][r] = 0.f;

    const int nIter = K / GBK;
    int cur = 0;
    for (int it = 0; it < nIter; it++) {
        CP_WAIT0();
        __syncthreads();
        if (it + 1 < nIter) {
            gemm_issue(A, B, N, K, rowBase, colBase, (it + 1) * GBK,
                       As, Bs, cur ^ 1, tid);
            CP_COMMIT();
        }

#pragma unroll
        for (int ks = 0; ks < GBK; ks += 8) {
            uint32_t af[4][4];
            uint32_t bf[4][2];
#pragma unroll
            for (int mi = 0; mi < 4; mi++) {
                int rb = warpRow * 64 + mi * 16;
                af[mi][0] = __float_as_uint(As[cur][rb + g][ks + t]);
                af[mi][1] = __float_as_uint(As[cur][rb + g + 8][ks + t]);
                af[mi][2] = __float_as_uint(As[cur][rb + g][ks + t + 4]);
                af[mi][3] = __float_as_uint(As[cur][rb + g + 8][ks + t + 4]);
            }
#pragma unroll
            for (int ni = 0; ni < 4; ni++) {
                int cb = warpCol * 32 + ni * 8 + g;
                bf[ni][0] = __float_as_uint(Bs[cur][ks + t][cb]);
                bf[ni][1] = __float_as_uint(Bs[cur][ks + t + 4][cb]);
            }
#pragma unroll
            for (int mi = 0; mi < 4; mi++)
#pragma unroll
                for (int ni = 0; ni < 4; ni++)
                    mma_tf32(acc[mi][ni][0], acc[mi][ni][1],
                             acc[mi][ni][2], acc[mi][ni][3],
                             af[mi][0], af[mi][1], af[mi][2], af[mi][3],
                             bf[ni][0], bf[ni][1]);
        }
        cur ^= 1;
    }

#pragma unroll
    for (int mi = 0; mi < 4; mi++) {
#pragma unroll
        for (int ni = 0; ni < 4; ni++) {
            int r0 = rowBase + warpRow * 64 + mi * 16 + g;
            int col = colBase + warpCol * 32 + ni * 8 + 2 * t;
            *(float2*)(C + (size_t)r0 * N + col) =
                make_float2(acc[mi][ni][0], acc[mi][ni][1]);
            *(float2*)(C + (size_t)(r0 + 8) * N + col) =
                make_float2(acc[mi][ni][2], acc[mi][ni][3]);
        }
    }
}

// Generic GEMM (output projection)
__global__ __launch_bounds__(256, 2) void gemm_tf32(
    int M, int N, int K,
    const float* __restrict__ A, const float* __restrict__ B,
    float* __restrict__ C)
{
    __shared__ float As[2][GBM][ASTRIDE];
    __shared__ float Bs[2][GBK][BSTRIDE];
    gemm_body(N, K, A, B, C, blockIdx.y * GBM, blockIdx.x * GBN, As, Bs);
}

// Fused QKV projection: bx 0-15 -> Wq, 16-19 -> Wk, 20-23 -> Wv
__global__ __launch_bounds__(256, 2) void gemm_qkv(
    const float* __restrict__ X,
    const float* __restrict__ Wq, const float* __restrict__ Wk,
    const float* __restrict__ Wv,
    float* __restrict__ Qo, float* __restrict__ Ko, float* __restrict__ Vo)
{
    __shared__ float As[2][GBM][ASTRIDE];
    __shared__ float Bs[2][GBK][BSTRIDE];

    int bx = blockIdx.x;
    const float* B;
    float* C;
    int N, colBase;
    if (bx < 16)      { B = Wq; C = Qo; N = DD;        colBase = bx * 128; }
    else if (bx < 20) { B = Wk; C = Ko; N = NKV * DH;  colBase = (bx - 16) * 128; }
    else              { B = Wv; C = Vo; N = NKV * DH;  colBase = (bx - 20) * 128; }

    gemm_body(N, DD, X, B, C, blockIdx.y * GBM, colBase, As, Bs);
}

// ---------------------------------------------------------------------------
// Trig table init
// ---------------------------------------------------------------------------
__global__ void trig_init()
{
    int idx = blockIdx.x * blockDim.x + threadIdx.x;
    if (idx >= TT * 32) return;
    int t = idx >> 5;
    int i = idx & 31;
    double inv = exp(-(double)i * (9.210340371976184 / 32.0));
    float ang = (float)t * (float)inv;
    float c, s;
    sincosf(ang, &s, &c);
    g_trig[idx] = make_float2(c, s);
}

// ---------------------------------------------------------------------------
// RoPE (q, k) + tf32 rounding; also rounds v. One launch.
// ---------------------------------------------------------------------------
__device__ __forceinline__ void rope_apply(float* __restrict__ X, int nheads, int idx)
{
    int i4 = (idx & 7) * 4;
    int hn = idx >> 3;
    int h = hn % nheads;
    int n = hn / nheads;
    int t = n & (TT - 1);

    const float2* tr = g_trig + t * 32 + i4;
    float2 t0 = tr[0], t1 = tr[1], t2 = tr[2], t3 = tr[3];

    float* p = X + (size_t)n * nheads * 64 + h * 64 + i4;
    float4 x1 = *(float4*)p;
    float4 x2 = *(float4*)(p + 32);

    float4 y1, y2;
    y1.x = rtf(x1.x * t0.x - x2.x * t0.y);  y2.x = rtf(x2.x * t0.x + x1.x * t0.y);
    y1.y = rtf(x1.y * t1.x - x2.y * t1.y);  y2.y = rtf(x2.y * t1.x + x1.y * t1.y);
    y1.z = rtf(x1.z * t2.x - x2.z * t2.y);  y2.z = rtf(x2.z * t2.x + x1.z * t2.y);
    y1.w = rtf(x1.w * t3.x - x2.w * t3.y);  y2.w = rtf(x2.w * t3.x + x1.w * t3.y);
    *(float4*)p = y1;
    *(float4*)(p + 32) = y2;
}

__global__ void rope_round(float* __restrict__ Qx, float* __restrict__ Kx,
                           float* __restrict__ Vx, int totq, int totk, int totv)
{
    int idx = blockIdx.x * blockDim.x + threadIdx.x;
    if (idx < totq) {
        rope_apply(Qx, NH, idx);
    } else if (idx < totq + totk) {
        rope_apply(Kx, NKV, idx - totq);
    } else if (idx < totq + totk + totv) {
        int i = idx - totq - totk;
        float4* p = (float4*)(Vx + (size_t)i * 4);
        float4 a = *p;
        a.x = rtf(a.x); a.y = rtf(a.y); a.z = rtf(a.z); a.w = rtf(a.w);
        *p = a;
    }
}

// ---------------------------------------------------------------------------
// Tensor-core flash attention (causal, GQA), cp.async double-buffered K/V.
// Inputs q/k/v MUST be tf32-rounded. Output ctx is tf32-rounded.
// ---------------------------------------------------------------------------
#define KV_BUF_FLOATS 8960   // 64*68 + 64*72
#define KS_OFF 0
#define VS_OFF 4352          // 64*68

__device__ __forceinline__ void attn_issue_kv(
    const float* __restrict__ K, const float* __restrict__ V,
    float* sm, int buf, int b, int kh, int s0, int tid)
{
#pragma unroll
    for (int i = 0; i < 4; i++) {
        int lin = tid + i * 256;
        int r = lin >> 4;
        int c4 = (lin & 15) * 4;
        size_t base = (size_t)(b * TT + s0 + r) * (NKV * DH) + kh * DH + c4;
        cp16(sm + buf * KV_BUF_FLOATS + KS_OFF + r * 68 + c4, K + base);
        cp16(sm + buf * KV_BUF_FLOATS + VS_OFF + r * 72 + c4, V + base);
    }
}

__global__ __launch_bounds__(256) void flash_attn_tc(
    const float* __restrict__ Q, const float* __restrict__ K,
    const float* __restrict__ V, float* __restrict__ O)
{
    extern __shared__ float sm[];

    const int tid = threadIdx.x;
    const int lane = tid & 31;
    const int warp = tid >> 5;
    const int g = lane >> 2;
    const int t = lane & 3;
    const int qt = blockIdx.x;
    const int h  = blockIdx.y;
    const int b  = blockIdx.z;
    const int kh = h / GG;
    const int rowBase = qt * 128 + warp * 16;
    const int kend = (qt + 1) * 128;

    // ---- stage Q through buffer-0 V region, extract A fragments ----
    uint32_t qa[8][4];
    {
        float (*Qs)[72] = (float(*)[72])(sm + VS_OFF);
#pragma unroll
        for (int half = 0; half < 2; half++) {
#pragma unroll
            for (int i = 0; i < 4; i++) {
                int lin = tid + i * 256;
                int r = lin >> 4;
                int c4 = (lin & 15) * 4;
                const float* src = Q + (size_t)(b * TT + qt * 128 + half * 64 + r) * DD
                                     + h * DH + c4;
                *(float4*)&Qs[r][c4] = *(const float4*)src;
            }
            __syncthreads();
            if ((warp >> 2) == half) {
                int lr = (warp & 3) * 16 + g;
#pragma unroll
                for (int kc = 0; kc < 8; kc++) {
                    qa[kc][0] = f2tf32(Qs[lr][kc * 8 + t] * 0.125f);
                    qa[kc][1] = f2tf32(Qs[lr + 8][kc * 8 + t] * 0.125f);
                    qa[kc][2] = f2tf32(Qs[lr][kc * 8 + t + 4] * 0.125f);
                    qa[kc][3] = f2tf32(Qs[lr + 8][kc * 8 + t + 4] * 0.125f);
                }
            }
            __syncthreads();
        }
    }

    // prologue: async-load KV tile 0
    attn_issue_kv(K, V, sm, 0, b, kh, 0, tid);
    CP_COMMIT();

    float oacc[8][4];
#pragma unroll
    for (int ni = 0; ni < 8; ni++)
#pragma unroll
        for (int r = 0; r < 4; r++) oacc[ni][r] = 0.f;
    float m0 = -1e30f, m1 = -1e30f, l0 = 0.f, l1 = 0.f;

    const int srcA = (lane & 28) | (t >> 1);
    const bool odd = (t & 1);

    int cur = 0;
    for (int s0 = 0; s0 < kend; s0 += 64) {
        CP_WAIT0();
        __syncthreads();
        if (s0 + 64 < kend) {
            attn_issue_kv(K, V, sm, cur ^ 1, b, kh, s0 + 64, tid);
            CP_COMMIT();
        }

        float (*Ks)[68] = (float(*)[68])(sm + cur * KV_BUF_FLOATS + KS_OFF);
        float (*Vs)[72] = (float(*)[72])(sm + cur * KV_BUF_FLOATS + VS_OFF);

        if (s0 <= rowBase + 15) {
            float sacc[8][4];
#pragma unroll
            for (int ni = 0; ni < 8; ni++) {
                sacc[ni][0] = 0.f; sacc[ni][1] = 0.f;
                sacc[ni][2] = 0.f; sacc[ni][3] = 0.f;
#pragma unroll
                for (int kc = 0; kc < 8; kc++) {
                    uint32_t b0 = __float_as_uint(Ks[ni * 8 + g][kc * 8 + t]);
                    uint32_t b1 = __float_as_uint(Ks[ni * 8 + g][kc * 8 + t + 4]);
                    mma_tf32(sacc[ni][0], sacc[ni][1], sacc[ni][2], sacc[ni][3],
                             qa[kc][0], qa[kc][1], qa[kc][2], qa[kc][3], b0, b1);
                }
            }

            if (s0 + 63 > rowBase) {
                int r0 = rowBase + g;
                int r1 = r0 + 8;
#pragma unroll
                for (int ni = 0; ni < 8; ni++) {
                    int c = s0 + ni * 8 + 2 * t;
                    if (c > r0)     sacc[ni][0] = -1e30f;
                    if (c + 1 > r0) sacc[ni][1] = -1e30f;
                    if (c > r1)     sacc[ni][2] = -1e30f;
                    if (c + 1 > r1) sacc[ni][3] = -1e30f;
                }
            }

            float mx0 = -1e30f, mx1 = -1e30f;
#pragma unroll
            for (int ni = 0; ni < 8; ni++) {
                mx0 = fmaxf(mx0, fmaxf(sacc[ni][0], sacc[ni][1]));
                mx1 = fmaxf(mx1, fmaxf(sacc[ni][2], sacc[ni][3]));
            }
            mx0 = fmaxf(mx0, __shfl_xor_sync(0xffffffffu, mx0, 1));
            mx0 = fmaxf(mx0, __shfl_xor_sync(0xffffffffu, mx0, 2));
            mx1 = fmaxf(mx1, __shfl_xor_sync(0xffffffffu, mx1, 1));
            mx1 = fmaxf(mx1, __shfl_xor_sync(0xffffffffu, mx1, 2));

            float mn0 = fmaxf(m0, mx0), mn1 = fmaxf(m1, mx1);
            float cr0 = __expf(m0 - mn0), cr1 = __expf(m1 - mn1);
            m0 = mn0; m1 = mn1;
            l0 *= cr0; l1 *= cr1;
#pragma unroll
            for (int ni = 0; ni < 8; ni++) {
                oacc[ni][0] *= cr0; oacc[ni][1] *= cr0;
                oacc[ni][2] *= cr1; oacc[ni][3] *= cr1;
            }
#pragma unroll
            for (int ni = 0; ni < 8; ni++) {
                sacc[ni][0] = __expf(sacc[ni][0] - m0);
                sacc[ni][1] = __expf(sacc[ni][1] - m0);
                sacc[ni][2] = __expf(sacc[ni][2] - m1);
                sacc[ni][3] = __expf(sacc[ni][3] - m1);
                l0 += sacc[ni][0] + sacc[ni][1];
                l1 += sacc[ni][2] + sacc[ni][3];
            }

#pragma unroll
            for (int kc = 0; kc < 8; kc++) {
                float v00 = __shfl_sync(0xffffffffu, sacc[kc][0], srcA);
                float v01 = __shfl_sync(0xffffffffu, sacc[kc][1], srcA);
                float v10 = __shfl_sync(0xffffffffu, sacc[kc][2], srcA);
                float v11 = __shfl_sync(0xffffffffu, sacc[kc][3], srcA);
                float w00 = __shfl_sync(0xffffffffu, sacc[kc][0], srcA + 2);
                float w01 = __shfl_sync(0xffffffffu, sacc[kc][1], srcA + 2);
                float w10 = __shfl_sync(0xffffffffu, sacc[kc][2], srcA + 2);
                float w11 = __shfl_sync(0xffffffffu, sacc[kc][3], srcA + 2);
                uint32_t a0 = f2tf32(odd ? v01 : v00);
                uint32_t a1 = f2tf32(odd ? v11 : v10);
                uint32_t a2 = f2tf32(odd ? w01 : w00);
                uint32_t a3 = f2tf32(odd ? w11 : w10);
#pragma unroll
                for (int ni = 0; ni < 8; ni++) {
                    uint32_t b0 = __float_as_uint(Vs[kc * 8 + t][ni * 8 + g]);
                    uint32_t b1 = __float_as_uint(Vs[kc * 8 + t + 4][ni * 8 + g]);
                    mma_tf32(oacc[ni][0], oacc[ni][1], oacc[ni][2], oacc[ni][3],
                             a0, a1, a2, a3, b0, b1);
                }
            }
        }
        cur ^= 1;
    }

    l0 += __shfl_xor_sync(0xffffffffu, l0, 1);
    l0 += __shfl_xor_sync(0xffffffffu, l0, 2);
    l1 += __shfl_xor_sync(0xffffffffu, l1, 1);
    l1 += __shfl_xor_sync(0xffffffffu, l1, 2);
    float inv0 = 1.f / l0, inv1 = 1.f / l1;

    int R0 = rowBase + g;
    float* o0 = O + (size_t)(b * TT + R0) * DD + h * DH;
    float* o1 = o0 + (size_t)8 * DD;
#pragma unroll
    for (int ni = 0; ni < 8; ni++) {
        *(float2*)(o0 + ni * 8 + 2 * t) =
            make_float2(rtf(oacc[ni][0] * inv0), rtf(oacc[ni][1] * inv0));
        *(float2*)(o1 + ni * 8 + 2 * t) =
            make_float2(rtf(oacc[ni][2] * inv1), rtf(oacc[ni][3] * inv1));
    }
}

// ---------------------------------------------------------------------------
// Launch
// ---------------------------------------------------------------------------
extern "C" void kernel_launch(void* const* d_in, const int* in_sizes, int n_in,
                              void* d_out, int out_size)
{
    const float* x  = (const float*)d_in[0];
    const float* Wq = (const float*)d_in[1];
    const float* Wk = (const float*)d_in[2];
    const float* Wv = (const float*)d_in[3];
    const float* Wo = (const float*)d_in[4];
    float* out = (float*)d_out;

    float *q, *k, *v, *ctx, *xr, *wqr, *wkr, *wvr, *wor;
    cudaGetSymbolAddress((void**)&q,   g_q);
    cudaGetSymbolAddress((void**)&k,   g_k);
    cudaGetSymbolAddress((void**)&v,   g_v);
    cudaGetSymbolAddress((void**)&ctx, g_ctx);
    cudaGetSymbolAddress((void**)&xr,  g_xr);
    cudaGetSymbolAddress((void**)&wqr, g_wqr);
    cudaGetSymbolAddress((void**)&wkr, g_wkr);
    cudaGetSymbolAddress((void**)&wvr, g_wvr);
    cudaGetSymbolAddress((void**)&wor, g_wor);

    static bool attr_set = false;
    if (!attr_set) {
        cudaFuncSetAttribute(flash_attn_tc,
                             cudaFuncAttributeMaxDynamicSharedMemorySize,
                             2 * KV_BUF_FLOATS * (int)sizeof(float));
        attr_set = true;
    }

    const int M = BB * TT;   // 4096

    trig_init<<<(TT * 32 + 255) / 256, 256>>>();

    // tf32-rounded copies of inputs
    {
        int nx = BB * TT * DD / 4;
        int nq = DD * DD / 4;
        int nk = DD * NKV * DH / 4;
        round_copy<<<(nx + 255) / 256, 256>>>((const float4*)x,  (float4*)xr,  nx);
        round_copy<<<(nq + 255) / 256, 256>>>((const float4*)Wq, (float4*)wqr, nq);
        round_copy<<<(nk + 255) / 256, 256>>>((const float4*)Wk, (float4*)wkr, nk);
        round_copy<<<(nk + 255) / 256, 256>>>((const float4*)Wv, (float4*)wvr, nk);
        round_copy<<<(nq + 255) / 256, 256>>>((const float4*)Wo, (float4*)wor, nq);
    }

    // Fused QKV projection (24 block columns: 16 Q, 4 K, 4 V)
    gemm_qkv<<<dim3(24, M / GBM), 256>>>(xr, wqr, wkr, wvr, q, k, v);

    // RoPE (q, k) + round v, one launch
    {
        int totq = M * NH * 8;
        int totk = M * NKV * 8;
        int totv = M * NKV * 16;
        rope_round<<<(totq + totk + totv + 255) / 256, 256>>>(q, k, v,
                                                              totq, totk, totv);
    }

    // Attention (tensor cores, cp.async double-buffered)
    flash_attn_tc<<<dim3(TT / 128, NH, BB), 256,
                    2 * KV_BUF_FLOATS * sizeof(float)>>>(q, k, v, ctx);

    // Output projection
    gemm_tf32<<<dim3(DD / GBN, M / GBM), 256>>>(M, DD, DD, ctx, wor, out);
}

// round 7
// speedup vs baseline: 5.2628x; 1.0367x over previous
#include <cuda_runtime.h>
#include <math.h>
#include <stdint.h>

// Problem constants
#define BB 2
#define TT 2048
#define DD 2048
#define NH 32
#define NKV 8
#define DH 64
#define GG 4   // NH / NKV

// Scratch (device globals)
__device__ float g_q[BB * TT * DD];
__device__ float g_k[BB * TT * NKV * DH];
__device__ float g_v[BB * TT * NKV * DH];
__device__ float g_vt[BB * NKV * DH * TT];    // V transposed: [b][kh][dh][t], tf32-rounded
__device__ float g_ctx[BB * TT * DD];
__device__ float g_xr[BB * TT * DD];          // tf32-rounded copies
__device__ float g_wqr[DD * DD];
__device__ float g_wkr[DD * NKV * DH];
__device__ float g_wvr[DD * NKV * DH];
__device__ float g_wor[DD * DD];
__device__ float2 g_trig[TT * 32];

__device__ __forceinline__ uint32_t f2tf32(float f) {
    uint32_t u;
    asm("cvt.rna.tf32.f32 %0, %1;" : "=r"(u) : "f"(f));
    return u;
}
__device__ __forceinline__ float rtf(float f) {
    return __uint_as_float(f2tf32(f));
}

__device__ __forceinline__ void mma_tf32(
    float& d0, float& d1, float& d2, float& d3,
    uint32_t a0, uint32_t a1, uint32_t a2, uint32_t a3,
    uint32_t b0, uint32_t b1)
{
    asm volatile(
        "mma.sync.aligned.m16n8k8.row.col.f32.tf32.tf32.f32 "
        "{%0,%1,%2,%3}, {%4,%5,%6,%7}, {%8,%9}, {%0,%1,%2,%3};"
        : "+f"(d0), "+f"(d1), "+f"(d2), "+f"(d3)
        : "r"(a0), "r"(a1), "r"(a2), "r"(a3), "r"(b0), "r"(b1));
}

__device__ __forceinline__ void ldsm4(
    uint32_t& r0, uint32_t& r1, uint32_t& r2, uint32_t& r3, uint32_t saddr)
{
    asm volatile("ldmatrix.sync.aligned.m8n8.x4.shared.b16 {%0,%1,%2,%3}, [%4];"
                 : "=r"(r0), "=r"(r1), "=r"(r2), "=r"(r3) : "r"(saddr));
}

__device__ __forceinline__ void cp16(void* dst, const void* src) {
    uint32_t d = (uint32_t)__cvta_generic_to_shared(dst);
    asm volatile("cp.async.cg.shared.global [%0], [%1], 16;" :: "r"(d), "l"(src));
}
#define CP_COMMIT() asm volatile("cp.async.commit_group;")
#define CP_WAIT0()  asm volatile("cp.async.wait_group 0;" ::: "memory")

// ---------------------------------------------------------------------------
// Elementwise tf32 round-copy
// ---------------------------------------------------------------------------
__global__ void round_copy(const float4* __restrict__ src,
                           float4* __restrict__ dst, int n4)
{
    int i = blockIdx.x * blockDim.x + threadIdx.x;
    if (i >= n4) return;
    float4 a = src[i];
    float4 r;
    r.x = rtf(a.x); r.y = rtf(a.y); r.z = rtf(a.z); r.w = rtf(a.w);
    dst[i] = r;
}

// ---------------------------------------------------------------------------
// TF32 GEMM, cp.async double-buffered, ldmatrix A-fragments.
// C = A @ B row-major, inputs pre-rounded to tf32.
// 128x128 tile, BK=16, 256 threads, warp tile 64x32.
// ---------------------------------------------------------------------------
#define GBM 128
#define GBN 128
#define GBK 16
#define ASTRIDE 20
#define BSTRIDE 136

__device__ __forceinline__ void gemm_issue(
    const float* __restrict__ A, const float* __restrict__ B,
    int N, int K, int rowBase, int colBase, int k0,
    float (*As)[GBM][ASTRIDE], float (*Bs)[GBK][BSTRIDE], int buf, int tid)
{
#pragma unroll
    for (int i = 0; i < 2; i++) {
        int idx = tid + i * 256;
        int row = idx >> 2;
        int c4 = (idx & 3) * 4;
        cp16(&As[buf][row][c4], A + (size_t)(rowBase + row) * K + k0 + c4);
        int brow = idx >> 5;
        int bc4 = (idx & 31) * 4;
        cp16(&Bs[buf][brow][bc4], B + (size_t)(k0 + brow) * N + colBase + bc4);
    }
}

__device__ __forceinline__ void gemm_body(
    int N, int K,
    const float* __restrict__ A, const float* __restrict__ B,
    float* __restrict__ C, int rowBase, int colBase,
    float (*As)[GBM][ASTRIDE], float (*Bs)[GBK][BSTRIDE])
{
    const int tid = threadIdx.x;
    const int lane = tid & 31;
    const int warp = tid >> 5;
    const int g = lane >> 2;
    const int t = lane & 3;
    const int warpRow = warp & 1;
    const int warpCol = warp >> 1;
    const int lm = lane >> 3;      // ldmatrix matrix id
    const int lr = lane & 7;       // ldmatrix row in matrix

    // lane offset within an A-tile LDSM: matrix lm -> rows +(lm&1)*8, cols +(lm>>1)*4
    const uint32_t aLaneOff = (uint32_t)((((lm & 1) * 8 + lr) * ASTRIDE + (lm >> 1) * 4) * 4);

    gemm_issue(A, B, N, K, rowBase, colBase, 0, As, Bs, 0, tid);
    CP_COMMIT();

    float acc[4][4][4];
#pragma unroll
    for (int mi = 0; mi < 4; mi++)
#pragma unroll
        for (int ni = 0; ni < 4; ni++)
#pragma unroll
            for (int r = 0; r < 4; r++) acc[mi][ni][r] = 0.f;

    const int nIter = K / GBK;
    int cur = 0;
    for (int it = 0; it < nIter; it++) {
        CP_WAIT0();
        __syncthreads();
        if (it + 1 < nIter) {
            gemm_issue(A, B, N, K, rowBase, colBase, (it + 1) * GBK,
                       As, Bs, cur ^ 1, tid);
            CP_COMMIT();
        }

        uint32_t as_base = (uint32_t)__cvta_generic_to_shared(&As[cur][0][0]);

#pragma unroll
        for (int ks = 0; ks < GBK; ks += 8) {
            uint32_t af[4][4];
            uint32_t bf[4][2];
#pragma unroll
            for (int mi = 0; mi < 4; mi++) {
                int rb = warpRow * 64 + mi * 16;
                ldsm4(af[mi][0], af[mi][1], af[mi][2], af[mi][3],
                      as_base + (uint32_t)((rb * ASTRIDE + ks) * 4) + aLaneOff);
            }
#pragma unroll
            for (int ni = 0; ni < 4; ni++) {
                int cb = warpCol * 32 + ni * 8 + g;
                bf[ni][0] = __float_as_uint(Bs[cur][ks + t][cb]);
                bf[ni][1] = __float_as_uint(Bs[cur][ks + t + 4][cb]);
            }
#pragma unroll
            for (int mi = 0; mi < 4; mi++)
#pragma unroll
                for (int ni = 0; ni < 4; ni++)
                    mma_tf32(acc[mi][ni][0], acc[mi][ni][1],
                             acc[mi][ni][2], acc[mi][ni][3],
                             af[mi][0], af[mi][1], af[mi][2], af[mi][3],
                             bf[ni][0], bf[ni][1]);
        }
        cur ^= 1;
    }

#pragma unroll
    for (int mi = 0; mi < 4; mi++) {
#pragma unroll
        for (int ni = 0; ni < 4; ni++) {
            int r0 = rowBase + warpRow * 64 + mi * 16 + g;
            int col = colBase + warpCol * 32 + ni * 8 + 2 * t;
            *(float2*)(C + (size_t)r0 * N + col) =
                make_float2(acc[mi][ni][0], acc[mi][ni][1]);
            *(float2*)(C + (size_t)(r0 + 8) * N + col) =
                make_float2(acc[mi][ni][2], acc[mi][ni][3]);
        }
    }
}

__global__ __launch_bounds__(256, 2) void gemm_tf32(
    int M, int N, int K,
    const float* __restrict__ A, const float* __restrict__ B,
    float* __restrict__ C)
{
    __shared__ float As[2][GBM][ASTRIDE];
    __shared__ float Bs[2][GBK][BSTRIDE];
    gemm_body(N, K, A, B, C, blockIdx.y * GBM, blockIdx.x * GBN, As, Bs);
}

__global__ __launch_bounds__(256, 2) void gemm_qkv(
    const float* __restrict__ X,
    const float* __restrict__ Wq, const float* __restrict__ Wk,
    const float* __restrict__ Wv,
    float* __restrict__ Qo, float* __restrict__ Ko, float* __restrict__ Vo)
{
    __shared__ float As[2][GBM][ASTRIDE];
    __shared__ float Bs[2][GBK][BSTRIDE];

    int bx = blockIdx.x;
    const float* B;
    float* C;
    int N, colBase;
    if (bx < 16)      { B = Wq; C = Qo; N = DD;        colBase = bx * 128; }
    else if (bx < 20) { B = Wk; C = Ko; N = NKV * DH;  colBase = (bx - 16) * 128; }
    else              { B = Wv; C = Vo; N = NKV * DH;  colBase = (bx - 20) * 128; }

    gemm_body(N, DD, X, B, C, blockIdx.y * GBM, colBase, As, Bs);
}

// ---------------------------------------------------------------------------
// Trig table init
// ---------------------------------------------------------------------------
__global__ void trig_init()
{
    int idx = blockIdx.x * blockDim.x + threadIdx.x;
    if (idx >= TT * 32) return;
    int t = idx >> 5;
    int i = idx & 31;
    double inv = exp(-(double)i * (9.210340371976184 / 32.0));
    float ang = (float)t * (float)inv;
    float c, s;
    sincosf(ang, &s, &c);
    g_trig[idx] = make_float2(c, s);
}

// ---------------------------------------------------------------------------
// RoPE (q, k) + V transpose (v -> vt, tf32-rounded). One launch.
// ---------------------------------------------------------------------------
__device__ __forceinline__ void rope_apply(float* __restrict__ X, int nheads, int idx)
{
    int i4 = (idx & 7) * 4;
    int hn = idx >> 3;
    int h = hn % nheads;
    int n = hn / nheads;
    int t = n & (TT - 1);

    const float2* tr = g_trig + t * 32 + i4;
    float2 t0 = tr[0], t1 = tr[1], t2 = tr[2], t3 = tr[3];

    float* p = X + (size_t)n * nheads * 64 + h * 64 + i4;
    float4 x1 = *(float4*)p;
    float4 x2 = *(float4*)(p + 32);

    float4 y1, y2;
    y1.x = rtf(x1.x * t0.x - x2.x * t0.y);  y2.x = rtf(x2.x * t0.x + x1.x * t0.y);
    y1.y = rtf(x1.y * t1.x - x2.y * t1.y);  y2.y = rtf(x2.y * t1.x + x1.y * t1.y);
    y1.z = rtf(x1.z * t2.x - x2.z * t2.y);  y2.z = rtf(x2.z * t2.x + x1.z * t2.y);
    y1.w = rtf(x1.w * t3.x - x2.w * t3.y);  y2.w = rtf(x2.w * t3.x + x1.w * t3.y);
    *(float4*)p = y1;
    *(float4*)(p + 32) = y2;
}

__global__ void rope_round(float* __restrict__ Qx, float* __restrict__ Kx,
                           const float* __restrict__ Vx, float* __restrict__ VT,
                           int totq, int totk, int totv)
{
    int idx = blockIdx.x * blockDim.x + threadIdx.x;
    if (idx < totq) {
        rope_apply(Qx, NH, idx);
    } else if (idx < totq + totk) {
        rope_apply(Kx, NKV, idx - totq);
    } else if (idx < totq + totk + totv) {
        // transpose + round V: i decomposed t-fastest for coalesced writes
        int i = idx - totq - totk;
        int t = i & (TT - 1);
        int r = i >> 11;           // (b*8+kh)*16 + d4
        int d4 = r & 15;
        int kb = r >> 4;           // b*NKV + kh
        const float* src = Vx + ((size_t)((kb >> 3) * TT + t) * (NKV * DH))
                              + (kb & 7) * DH + d4 * 4;
        float4 a = *(const float4*)src;
        float* dst = VT + ((size_t)kb * DH + d4 * 4) * TT + t;
        dst[0 * TT] = rtf(a.x);
        dst[1 * TT] = rtf(a.y);
        dst[2 * TT] = rtf(a.z);
        dst[3 * TT] = rtf(a.w);
    }
}

// ---------------------------------------------------------------------------
// Tensor-core flash attention (causal, GQA), cp.async double-buffered,
// ldmatrix B-fragments for both QK^T (K seq-major) and PV (V^T dh-major).
// SMEM per buffer: Ks[64][68] + VTs[64][68].
// ---------------------------------------------------------------------------
#define KV_BUF_FLOATS 8704   // 2 * 64*68
#define KS_OFF 0
#define VS_OFF 4352          // 64*68
#define KSTRIDE 68

__device__ __forceinline__ void attn_issue_kv(
    const float* __restrict__ K, const float* __restrict__ VT,
    float* sm, int buf, int b, int kh, int s0, int tid)
{
    size_t vtrow = ((size_t)(b * NKV + kh)) * DH;
#pragma unroll
    for (int i = 0; i < 4; i++) {
        int lin = tid + i * 256;
        int r = lin >> 4;
        int c4 = (lin & 15) * 4;
        cp16(sm + buf * KV_BUF_FLOATS + KS_OFF + r * KSTRIDE + c4,
             K + (size_t)(b * TT + s0 + r) * (NKV * DH) + kh * DH + c4);
        cp16(sm + buf * KV_BUF_FLOATS + VS_OFF + r * KSTRIDE + c4,
             VT + (vtrow + r) * TT + s0 + c4);
    }
}

__global__ __launch_bounds__(256) void flash_attn_tc(
    const float* __restrict__ Q, const float* __restrict__ K,
    const float* __restrict__ VT, float* __restrict__ O)
{
    extern __shared__ float sm[];

    const int tid = threadIdx.x;
    const int lane = tid & 31;
    const int warp = tid >> 5;
    const int g = lane >> 2;
    const int t = lane & 3;
    const int lm = lane >> 3;
    const int lr = lane & 7;
    const int qt = blockIdx.x;
    const int h  = blockIdx.y;
    const int b  = blockIdx.z;
    const int kh = h / GG;
    const int rowBase = qt * 128 + warp * 16;
    const int kend = (qt + 1) * 128;

    // ---- stage Q through buffer-0 VT region, extract A fragments ----
    uint32_t qa[8][4];
    {
        float (*Qs)[KSTRIDE] = (float(*)[KSTRIDE])(sm + VS_OFF);
#pragma unroll
        for (int half = 0; half < 2; half++) {
#pragma unroll
            for (int i = 0; i < 4; i++) {
                int lin = tid + i * 256;
                int r = lin >> 4;
                int c4 = (lin & 15) * 4;
                const float* src = Q + (size_t)(b * TT + qt * 128 + half * 64 + r) * DD
                                     + h * DH + c4;
                *(float4*)&Qs[r][c4] = *(const float4*)src;
            }
            __syncthreads();
            if ((warp >> 2) == half) {
                int qlr = (warp & 3) * 16 + g;
#pragma unroll
                for (int kc = 0; kc < 8; kc++) {
                    qa[kc][0] = f2tf32(Qs[qlr][kc * 8 + t] * 0.125f);
                    qa[kc][1] = f2tf32(Qs[qlr + 8][kc * 8 + t] * 0.125f);
                    qa[kc][2] = f2tf32(Qs[qlr][kc * 8 + t + 4] * 0.125f);
                    qa[kc][3] = f2tf32(Qs[qlr + 8][kc * 8 + t + 4] * 0.125f);
                }
            }
            __syncthreads();
        }
    }

    attn_issue_kv(K, VT, sm, 0, b, kh, 0, tid);
    CP_COMMIT();

    float oacc[8][4];
#pragma unroll
    for (int ni = 0; ni < 8; ni++)
#pragma unroll
        for (int r = 0; r < 4; r++) oacc[ni][r] = 0.f;
    float m0 = -1e30f, m1 = -1e30f, l0 = 0.f, l1 = 0.f;

    const int srcA = (lane & 28) | (t >> 1);
    const bool odd = (t & 1);

    // ldmatrix lane offsets (bytes):
    // K (S-phase): LDSM j covers kc=2j,2j+1, halves lo/hi:
    //   matrix m: kc += m>>1, half = m&1; row = ni*8+lr
    const uint32_t kLaneOff = (uint32_t)((lr * KSTRIDE + (lm >> 1) * 8 + (lm & 1) * 4) * 4);
    // VT (PV-phase): LDSM jj covers ni=2jj,2jj+1:
    //   matrix m: ni += m>>1, half = m&1; row = ni*8+lr, col = kc*8+half*4
    const uint32_t vLaneOff = (uint32_t)((((lm >> 1) * 8 + lr) * KSTRIDE + (lm & 1) * 4) * 4);

    int cur = 0;
    for (int s0 = 0; s0 < kend; s0 += 64) {
        CP_WAIT0();
        __syncthreads();
        if (s0 + 64 < kend) {
            attn_issue_kv(K, VT, sm, cur ^ 1, b, kh, s0 + 64, tid);
            CP_COMMIT();
        }

        if (s0 <= rowBase + 15) {
            uint32_t ks_base = (uint32_t)__cvta_generic_to_shared(
                sm + cur * KV_BUF_FLOATS + KS_OFF);
            uint32_t vs_base = (uint32_t)__cvta_generic_to_shared(
                sm + cur * KV_BUF_FLOATS + VS_OFF);

            // ---- S = Q @ K^T ----
            float sacc[8][4];
#pragma unroll
            for (int ni = 0; ni < 8; ni++) {
                sacc[ni][0] = 0.f; sacc[ni][1] = 0.f;
                sacc[ni][2] = 0.f; sacc[ni][3] = 0.f;
#pragma unroll
                for (int j = 0; j < 4; j++) {
                    uint32_t b0a, b1a, b0b, b1b;
                    ldsm4(b0a, b1a, b0b, b1b,
                          ks_base + (uint32_t)((ni * 8 * KSTRIDE + j * 16) * 4) + kLaneOff);
                    mma_tf32(sacc[ni][0], sacc[ni][1], sacc[ni][2], sacc[ni][3],
                             qa[2*j][0], qa[2*j][1], qa[2*j][2], qa[2*j][3], b0a, b1a);
                    mma_tf32(sacc[ni][0], sacc[ni][1], sacc[ni][2], sacc[ni][3],
                             qa[2*j+1][0], qa[2*j+1][1], qa[2*j+1][2], qa[2*j+1][3], b0b, b1b);
                }
            }

            // ---- causal mask ----
            if (s0 + 63 > rowBase) {
                int r0 = rowBase + g;
                int r1 = r0 + 8;
#pragma unroll
                for (int ni = 0; ni < 8; ni++) {
                    int c = s0 + ni * 8 + 2 * t;
                    if (c > r0)     sacc[ni][0] = -1e30f;
                    if (c + 1 > r0) sacc[ni][1] = -1e30f;
                    if (c > r1)     sacc[ni][2] = -1e30f;
                    if (c + 1 > r1) sacc[ni][3] = -1e30f;
                }
            }

            // ---- online softmax ----
            float mx0 = -1e30f, mx1 = -1e30f;
#pragma unroll
            for (int ni = 0; ni < 8; ni++) {
                mx0 = fmaxf(mx0, fmaxf(sacc[ni][0], sacc[ni][1]));
                mx1 = fmaxf(mx1, fmaxf(sacc[ni][2], sacc[ni][3]));
            }
            mx0 = fmaxf(mx0, __shfl_xor_sync(0xffffffffu, mx0, 1));
            mx0 = fmaxf(mx0, __shfl_xor_sync(0xffffffffu, mx0, 2));
            mx1 = fmaxf(mx1, __shfl_xor_sync(0xffffffffu, mx1, 1));
            mx1 = fmaxf(mx1, __shfl_xor_sync(0xffffffffu, mx1, 2));

            float mn0 = fmaxf(m0, mx0), mn1 = fmaxf(m1, mx1);
            float cr0 = __expf(m0 - mn0), cr1 = __expf(m1 - mn1);
            m0 = mn0; m1 = mn1;
            l0 *= cr0; l1 *= cr1;
#pragma unroll
            for (int ni = 0; ni < 8; ni++) {
                oacc[ni][0] *= cr0; oacc[ni][1] *= cr0;
                oacc[ni][2] *= cr1; oacc[ni][3] *= cr1;
            }
#pragma unroll
            for (int ni = 0; ni < 8; ni++) {
                sacc[ni][0] = __expf(sacc[ni][0] - m0);
                sacc[ni][1] = __expf(sacc[ni][1] - m0);
                sacc[ni][2] = __expf(sacc[ni][2] - m1);
                sacc[ni][3] = __expf(sacc[ni][3] - m1);
                l0 += sacc[ni][0] + sacc[ni][1];
                l1 += sacc[ni][2] + sacc[ni][3];
            }

            // ---- O += P @ V (ldmatrix on VT) ----
#pragma unroll
            for (int kc = 0; kc < 8; kc++) {
                float v00 = __shfl_sync(0xffffffffu, sacc[kc][0], srcA);
                float v01 = __shfl_sync(0xffffffffu, sacc[kc][1], srcA);
                float v10 = __shfl_sync(0xffffffffu, sacc[kc][2], srcA);
                float v11 = __shfl_sync(0xffffffffu, sacc[kc][3], srcA);
                float w00 = __shfl_sync(0xffffffffu, sacc[kc][0], srcA + 2);
                float w01 = __shfl_sync(0xffffffffu, sacc[kc][1], srcA + 2);
                float w10 = __shfl_sync(0xffffffffu, sacc[kc][2], srcA + 2);
                float w11 = __shfl_sync(0xffffffffu, sacc[kc][3], srcA + 2);
                uint32_t a0 = f2tf32(odd ? v01 : v00);
                uint32_t a1 = f2tf32(odd ? v11 : v10);
                uint32_t a2 = f2tf32(odd ? w01 : w00);
                uint32_t a3 = f2tf32(odd ? w11 : w10);
#pragma unroll
                for (int jj = 0; jj < 4; jj++) {
                    uint32_t c0, c1, c2, c3;
                    ldsm4(c0, c1, c2, c3,
                          vs_base + (uint32_t)((jj * 16 * KSTRIDE + kc * 8) * 4) + vLaneOff);
                    mma_tf32(oacc[2*jj][0], oacc[2*jj][1], oacc[2*jj][2], oacc[2*jj][3],
                             a0, a1, a2, a3, c0, c1);
                    mma_tf32(oacc[2*jj+1][0], oacc[2*jj+1][1], oacc[2*jj+1][2], oacc[2*jj+1][3],
                             a0, a1, a2, a3, c2, c3);
                }
            }
        }
        cur ^= 1;
    }

    l0 += __shfl_xor_sync(0xffffffffu, l0, 1);
    l0 += __shfl_xor_sync(0xffffffffu, l0, 2);
    l1 += __shfl_xor_sync(0xffffffffu, l1, 1);
    l1 += __shfl_xor_sync(0xffffffffu, l1, 2);
    float inv0 = 1.f / l0, inv1 = 1.f / l1;

    int R0 = rowBase + g;
    float* o0 = O + (size_t)(b * TT + R0) * DD + h * DH;
    float* o1 = o0 + (size_t)8 * DD;
#pragma unroll
    for (int ni = 0; ni < 8; ni++) {
        *(float2*)(o0 + ni * 8 + 2 * t) =
            make_float2(rtf(oacc[ni][0] * inv0), rtf(oacc[ni][1] * inv0));
        *(float2*)(o1 + ni * 8 + 2 * t) =
            make_float2(rtf(oacc[ni][2] * inv1), rtf(oacc[ni][3] * inv1));
    }
}

// ---------------------------------------------------------------------------
// Launch
// ---------------------------------------------------------------------------
extern "C" void kernel_launch(void* const* d_in, const int* in_sizes, int n_in,
                              void* d_out, int out_size)
{
    const float* x  = (const float*)d_in[0];
    const float* Wq = (const float*)d_in[1];
    const float* Wk = (const float*)d_in[2];
    const float* Wv = (const float*)d_in[3];
    const float* Wo = (const float*)d_in[4];
    float* out = (float*)d_out;

    float *q, *k, *v, *vt, *ctx, *xr, *wqr, *wkr, *wvr, *wor;
    cudaGetSymbolAddress((void**)&q,   g_q);
    cudaGetSymbolAddress((void**)&k,   g_k);
    cudaGetSymbolAddress((void**)&v,   g_v);
    cudaGetSymbolAddress((void**)&vt,  g_vt);
    cudaGetSymbolAddress((void**)&ctx, g_ctx);
    cudaGetSymbolAddress((void**)&xr,  g_xr);
    cudaGetSymbolAddress((void**)&wqr, g_wqr);
    cudaGetSymbolAddress((void**)&wkr, g_wkr);
    cudaGetSymbolAddress((void**)&wvr, g_wvr);
    cudaGetSymbolAddress((void**)&wor, g_wor);

    static bool attr_set = false;
    if (!attr_set) {
        cudaFuncSetAttribute(flash_attn_tc,
                             cudaFuncAttributeMaxDynamicSharedMemorySize,
                             2 * KV_BUF_FLOATS * (int)sizeof(float));
        attr_set = true;
    }

    const int M = BB * TT;   // 4096

    trig_init<<<(TT * 32 + 255) / 256, 256>>>();

    // tf32-rounded copies of inputs
    {
        int nx = BB * TT * DD / 4;
        int nq = DD * DD / 4;
        int nk = DD * NKV * DH / 4;
        round_copy<<<(nx + 255) / 256, 256>>>((const float4*)x,  (float4*)xr,  nx);
        round_copy<<<(nq + 255) / 256, 256>>>((const float4*)Wq, (float4*)wqr, nq);
        round_copy<<<(nk + 255) / 256, 256>>>((const float4*)Wk, (float4*)wkr, nk);
        round_copy<<<(nk + 255) / 256, 256>>>((const float4*)Wv, (float4*)wvr, nk);
        round_copy<<<(nq + 255) / 256, 256>>>((const float4*)Wo, (float4*)wor, nq);
    }

    // Fused QKV projection
    gemm_qkv<<<dim3(24, M / GBM), 256>>>(xr, wqr, wkr, wvr, q, k, v);

    // RoPE (q, k) + V transpose/round, one launch
    {
        int totq = M * NH * 8;
        int totk = M * NKV * 8;
        int totv = M * NKV * 16;
        rope_round<<<(totq + totk + totv + 255) / 256, 256>>>(q, k, v, vt,
                                                              totq, totk, totv);
    }

    // Attention
    flash_attn_tc<<<dim3(TT / 128, NH, BB), 256,
                    2 * KV_BUF_FLOATS * sizeof(float)>>>(q, k, vt, ctx);

    // Output projection
    gemm_tf32<<<dim3(DD / GBN, M / GBM), 256>>>(M, DD, DD, ctx, wor, out);
}